// round 13
// baseline (speedup 1.0000x reference)
#include <cuda_runtime.h>
#include <cstdint>

#define U_DIM 768
#define T_DIM 1024
#define B_DIM 2
#define BT    2048
#define E_DIM 8
#define L_DIM 16
#define V_DIM 32000
#define EPS_F 1e-6f
#define UU    589824L
#define TU    786432L
#define HN    1572864L

#define OFF_WIN  0L
#define OFF_QKV  (UU)
#define OFF_F1   (OFF_QKV + 48L*UU)
#define OFF_F2   (OFF_F1 + 16L*UU)
#define OFF_EW   (OFF_F2 + 16L*UU)
#define OFF_WLOG (OFF_EW + 128L*UU)
#define W_TOTAL  (OFF_WLOG + 32000L*768L)

// weight scale arena offsets (one per B-row)
#define SC_WIN  0
#define SC_QKV  768          // 16*2304
#define SC_F1   37632        // 16*768
#define SC_F2   49920
#define SC_EW   62208
#define SC_WLOG 74496
#define SC_TOT  106496

__device__ char g_w1[W_TOTAL], g_w0[W_TOTAL];
__device__ float g_wsc[SC_TOT];

__device__ float g_h[HN], g_h0[HN], g_hA[HN], g_hM[HN], g_n[HN];
__device__ float g_mo[3*HN];
__device__ float g_qf[HN], g_ktf[HN], g_vtf[HN];
__device__ float g_ksum[B_DIM*U_DIM], g_den[BT], g_gate[BT*E_DIM];

__device__ char g_n1[HN],  g_n0[HN];
__device__ char g_x1[HN],  g_x0[HN];
__device__ char g_q1[HN],  g_q0[HN];
__device__ char g_kt1[HN], g_kt0[HN];
__device__ char g_vt1[HN], g_vt0[HN];
__device__ char g_kv1[B_DIM*UU], g_kv0[B_DIM*UU];
__device__ char g_f11[HN], g_f10[HN];
__device__ char g_am1[BT*6144L], g_am0[BT*6144L];
__device__ float g_sn[BT], g_sx[BT], g_sq[BT], g_skt[1536], g_svt[1536];
__device__ float g_skv[1536], g_sf1[BT], g_sam[BT];

__device__ __forceinline__ uint32_t smem_u32(const void* p) {
    uint32_t a;
    asm("{ .reg .u64 t; cvta.to.shared.u64 t, %1; cvt.u32.u64 %0, t; }" : "=r"(a) : "l"(p));
    return a;
}
__device__ __forceinline__ float warpSum(float v) {
    #pragma unroll
    for (int o = 16; o > 0; o >>= 1) v += __shfl_xor_sync(0xffffffffu, v, o);
    return v;
}
__device__ __forceinline__ float warpMax(float v) {
    #pragma unroll
    for (int o = 16; o > 0; o >>= 1) v = fmaxf(v, __shfl_xor_sync(0xffffffffu, v, o));
    return v;
}
__device__ __forceinline__ void quant2(float x, float inv, char& a1, char& a0) {
    float q = x * inv;
    float r1 = rintf(q);
    a1 = (char)(int)r1;
    a0 = (char)(int)rintf((q - r1) * 127.f);
}

struct GArgs {
    const char *A1, *A0, *B1, *B0;
    const float *sA, *sB;
    int saZ, sbZ;
    int N, K, kSplit, SK;
    long aZ, bZ, cZ;
    const float *bias, *bias2, *bias3;
    float *outF, *outF2;
    float *qf, *ktf, *vtf;
};

#define ROWB 80
#define TBB  (128 * ROWB)      // 10240
#define DSM  (12 * TBB)        // 122880

#define MMA_S8(dv, afv, bfv) \
    asm volatile("mma.sync.aligned.m16n8k32.row.col.s32.s8.s8.s32 " \
        "{%0,%1,%2,%3}, {%4,%5,%6,%7}, {%8,%9}, {%0,%1,%2,%3};" \
        : "+r"((dv)[0]), "+r"((dv)[1]), "+r"((dv)[2]), "+r"((dv)[3]) \
        : "r"((afv)[0]), "r"((afv)[1]), "r"((afv)[2]), "r"((afv)[3]), \
          "r"((bfv)[0]), "r"((bfv)[1]))

// EPI: 1 h0(out+copy), 2 scaled partial, 7 logits x2, 8 qkv(q fp32 / kT / vT fp32)
template<int EPI>
__global__ __launch_bounds__(256)
void mma_gemm(GArgs g)
{
    extern __shared__ char smem[];
    uint32_t sb = smem_u32(smem);
    const int tid = threadIdx.x, wid = tid >> 5, lane = tid & 31;
    const int wm = wid >> 2, wn = wid & 3;
    const int z = blockIdx.z;
    const int zB = g.SK > 1 ? z / g.SK : z;
    const int zS = g.SK > 1 ? z % g.SK : 0;
    const int row0 = blockIdx.y * 128, col0 = blockIdx.x * 128;
    const int Nn = g.N, K = g.K;

    const char* A1 = g.A1 + (long)zB * g.aZ;
    const char* A0 = g.A0 + (long)zB * g.aZ;
    const char* B1 = g.B1 + (long)zB * g.bZ;
    const char* B0 = g.B0 + (long)zB * g.bZ;
    const int kbase = g.kSplit ? zS * g.kSplit : 0;
    const int CH = (g.kSplit ? g.kSplit : K) >> 6;

    int acc1[4][4][4], acc2[4][4][4];
    #pragma unroll
    for (int a = 0; a < 4; a++)
        #pragma unroll
        for (int b = 0; b < 4; b++)
            #pragma unroll
            for (int c = 0; c < 4; c++) { acc1[a][b][c] = 0; acc2[a][b][c] = 0; }

    auto issue = [&](int c, int s) {
        int k0 = kbase + (c << 6);
        const char* srcs[4] = {
            A1 + (long)row0 * K + k0, A0 + (long)row0 * K + k0,
            B1 + (long)col0 * K + k0, B0 + (long)col0 * K + k0 };
        #pragma unroll
        for (int t = 0; t < 4; t++) {
            uint32_t dst = sb + (uint32_t)(s * 4 + t) * TBB;
            #pragma unroll
            for (int i = 0; i < 2; i++) {
                int idx = tid + (i << 8);      // 0..511
                int r = idx >> 2, cc = idx & 3;
                uint32_t doff = (uint32_t)(r * ROWB + cc * 16);
                const void* sp = srcs[t] + (long)r * K + cc * 16;
                asm volatile("cp.async.cg.shared.global [%0], [%1], 16;"
                             :: "r"(dst + doff), "l"(sp));
            }
        }
        asm volatile("cp.async.commit_group;");
    };

    issue(0, 0);
    if (CH > 1) issue(1, 1);
    for (int c = 0; c < CH; c++) {
        int s = c % 3;
        if (c + 2 < CH) { issue(c + 2, (c + 2) % 3); asm volatile("cp.async.wait_group 2;"); }
        else if (c + 1 < CH) { asm volatile("cp.async.wait_group 1;"); }
        else { asm volatile("cp.async.wait_group 0;"); }
        __syncthreads();
        uint32_t bA1 = sb + (uint32_t)(s * 4 + 0) * TBB;
        uint32_t bA0 = sb + (uint32_t)(s * 4 + 1) * TBB;
        uint32_t bB1 = sb + (uint32_t)(s * 4 + 2) * TBB;
        uint32_t bB0 = sb + (uint32_t)(s * 4 + 3) * TBB;
        #pragma unroll
        for (int ks = 0; ks < 2; ks++) {
            int kb = ks * 32;
            int aoff = (wm * 64 + (lane & 15)) * ROWB + kb + ((lane >> 4) << 4);
            int boff = (wn * 32 + (lane & 7)) * ROWB + kb + (((lane >> 3) & 1) << 4);
            uint32_t a1f[4][4], a0f[4][4], bf_[4][2];
            #pragma unroll
            for (int mt = 0; mt < 4; mt++) {
                uint32_t ad = bA1 + (uint32_t)(aoff + mt * 16 * ROWB);
                asm volatile("ldmatrix.sync.aligned.m8n8.x4.shared.b16 {%0,%1,%2,%3}, [%4];"
                    : "=r"(a1f[mt][0]), "=r"(a1f[mt][1]), "=r"(a1f[mt][2]), "=r"(a1f[mt][3]) : "r"(ad));
            }
            #pragma unroll
            for (int mt = 0; mt < 4; mt++) {
                uint32_t ad = bA0 + (uint32_t)(aoff + mt * 16 * ROWB);
                asm volatile("ldmatrix.sync.aligned.m8n8.x4.shared.b16 {%0,%1,%2,%3}, [%4];"
                    : "=r"(a0f[mt][0]), "=r"(a0f[mt][1]), "=r"(a0f[mt][2]), "=r"(a0f[mt][3]) : "r"(ad));
            }
            #pragma unroll
            for (int nt = 0; nt < 4; nt++) {
                uint32_t bd = bB1 + (uint32_t)(boff + nt * 8 * ROWB);
                asm volatile("ldmatrix.sync.aligned.m8n8.x2.shared.b16 {%0,%1}, [%2];"
                    : "=r"(bf_[nt][0]), "=r"(bf_[nt][1]) : "r"(bd));
            }
            // P1: A1*B1 -> acc1 ; P3: A0*B1 -> acc2
            #pragma unroll
            for (int mt = 0; mt < 4; mt++)
                #pragma unroll
                for (int nt = 0; nt < 4; nt++) {
                    MMA_S8(acc1[mt][nt], a1f[mt], bf_[nt]);
                    MMA_S8(acc2[mt][nt], a0f[mt], bf_[nt]);
                }
            // P2: A1*B0 -> acc2
            #pragma unroll
            for (int nt = 0; nt < 4; nt++) {
                uint32_t bd = bB0 + (uint32_t)(boff + nt * 8 * ROWB);
                asm volatile("ldmatrix.sync.aligned.m8n8.x2.shared.b16 {%0,%1}, [%2];"
                    : "=r"(bf_[nt][0]), "=r"(bf_[nt][1]) : "r"(bd));
            }
            #pragma unroll
            for (int mt = 0; mt < 4; mt++)
                #pragma unroll
                for (int nt = 0; nt < 4; nt++)
                    MMA_S8(acc2[mt][nt], a1f[mt], bf_[nt]);
        }
        __syncthreads();
    }

    // ---------------- epilogue: v = sA*sB*(acc1 + acc2/127) ----------------
    const float* sAp = g.sA + (long)zB * g.saZ;
    const float* sBp = g.sB + (long)zB * g.sbZ;

    if (EPI == 8) {
        const int blkN = col0 / 768;
        const int cc0  = col0 - blkN * 768;
        if (blkN == 0) {
            #pragma unroll
            for (int mt = 0; mt < 4; mt++)
                #pragma unroll
                for (int half = 0; half < 2; half++) {
                    int rg = row0 + wm * 64 + mt * 16 + (lane >> 2) + half * 8;
                    float sa = sAp[rg];
                    #pragma unroll
                    for (int nt = 0; nt < 4; nt++) {
                        int col = cc0 + wn * 32 + nt * 8 + 2 * (lane & 3);
                        #pragma unroll
                        for (int jj = 0; jj < 2; jj++) {
                            float sc = sa * __ldg(&sBp[col + jj]);
                            float v = ((float)acc1[mt][nt][half*2+jj]
                                     + (float)acc2[mt][nt][half*2+jj] * (1.f/127.f)) * sc;
                            float t = v + __ldg(&g.bias[col + jj]);
                            float o = (t > 0.f) ? (t + 1.f) : __expf(t);
                            g.qf[(long)rg * 768 + col + jj] = o;
                        }
                    }
                }
        } else {
            const float* bp = (blkN == 1) ? g.bias2 : g.bias3;
            float* tile = (float*)smem;
            #pragma unroll
            for (int mt = 0; mt < 4; mt++)
                #pragma unroll
                for (int half = 0; half < 2; half++) {
                    int r = wm*64 + mt*16 + (lane>>2) + half*8;
                    float sa = sAp[row0 + r];
                    #pragma unroll
                    for (int nt = 0; nt < 4; nt++) {
                        int cl = wn*32 + nt*8 + 2*(lane&3);
                        #pragma unroll
                        for (int jj = 0; jj < 2; jj++) {
                            float sc = sa * __ldg(&sBp[col0 + cl + jj]);
                            float v = ((float)acc1[mt][nt][half*2+jj]
                                     + (float)acc2[mt][nt][half*2+jj] * (1.f/127.f)) * sc;
                            float t = v + __ldg(&bp[cc0 + cl + jj]);
                            if (blkN == 1) t = (t > 0.f) ? (t + 1.f) : __expf(t);
                            tile[r * 130 + cl + jj] = t;
                        }
                    }
                }
            __syncthreads();
            float* df = (blkN == 1) ? g.ktf : g.vtf;
            int u_l = tid & 127, th = tid >> 7;
            int bb = row0 >> 10, t0 = row0 & 1023;
            long rowbase = ((long)(bb * 768 + cc0 + u_l)) * 1024 + t0 + th * 64;
            #pragma unroll
            for (int j = 0; j < 64; j += 4) {
                float4 vv;
                vv.x = tile[(th*64 + j + 0) * 130 + u_l];
                vv.y = tile[(th*64 + j + 1) * 130 + u_l];
                vv.z = tile[(th*64 + j + 2) * 130 + u_l];
                vv.w = tile[(th*64 + j + 3) * 130 + u_l];
                *(float4*)(df + rowbase + j) = vv;
            }
        }
        return;
    }

    float* outF = g.outF + (long)z * g.cZ;
    #pragma unroll
    for (int mt = 0; mt < 4; mt++)
        #pragma unroll
        for (int half = 0; half < 2; half++) {
            int rg = row0 + wm * 64 + mt * 16 + (lane >> 2) + half * 8;
            float sa = sAp[rg];
            #pragma unroll
            for (int nt = 0; nt < 4; nt++) {
                int col = col0 + wn * 32 + nt * 8 + 2 * (lane & 3);
                #pragma unroll
                for (int jj = 0; jj < 2; jj++) {
                    float sc = sa * __ldg(&sBp[col + jj]);
                    float v = ((float)acc1[mt][nt][half*2+jj]
                             + (float)acc2[mt][nt][half*2+jj] * (1.f/127.f)) * sc;
                    long idx = (long)rg * Nn + col + jj;
                    if (EPI == 2) outF[idx] = v;
                    else if (EPI == 7) outF[idx] = v * 2.0f;
                    else { outF[idx] = v; g.outF2[idx] = v; }
                }
            }
        }
}

// ---------- weight quantizer: dst[n][k] = quant(src[k][n]) ----------
__global__ __launch_bounds__(256)
void wquant(const float* __restrict__ src, char* d1, char* d0, float* sc,
            int K, int N, long srcZ, long dstZ, int scZ)
{
    __shared__ float tile[256][33];
    __shared__ float cm8[8][32];
    __shared__ float cinv[32], cmax[32];
    int z = blockIdx.z;
    const float* s = src + (long)z * srcZ;
    char* dd1 = d1 + (long)z * dstZ;
    char* dd0 = d0 + (long)z * dstZ;
    float* scp = sc + (long)z * scZ;
    int n0 = blockIdx.x * 32;
    int tn = threadIdx.x & 31, tk = threadIdx.x >> 5;   // col, k-lane(8)
    // phase 1: column max
    float m = 0.f;
    for (int k = tk; k < K; k += 8) m = fmaxf(m, fabsf(s[(long)k * N + n0 + tn]));
    cm8[tk][tn] = m;
    __syncthreads();
    if (threadIdx.x < 32) {
        float mm = 0.f;
        #pragma unroll
        for (int i = 0; i < 8; i++) mm = fmaxf(mm, cm8[i][threadIdx.x]);
        cmax[threadIdx.x] = mm;
        cinv[threadIdx.x] = (mm > 0.f) ? (127.f / mm) : 0.f;
        scp[n0 + threadIdx.x] = (mm > 0.f) ? (mm / 127.f) : 1e-30f;
    }
    __syncthreads();
    // phase 2: tile through k, write coalesced
    for (int kc = 0; kc < K; kc += 256) {
        #pragma unroll
        for (int i = 0; i < 8; i++) {
            int k = kc + tk + i * 8 * 4;   // careful: cover 256 k with 8 iters of 32 k? no:
        }
        // simpler: 8 iterations, each loads 32 k x 32 n sub-rows
        for (int i = 0; i < 8; i++) {
            int k = kc + i * 32 + tk * 4;  // tk 0..7 -> 4 k each? mismatch; use direct:
            (void)k;
        }
        // direct load: idx over 256x32 elements, 8192/256 = 32 iters is too many.
        // Use: each thread loads 32 elements: k = kc + tk*32 + j, n = tn  (strided but L2-local)
        for (int j = 0; j < 32; j++) {
            int k = kc + tk * 32 + j;
            tile[tk * 32 + j][tn] = s[(long)k * N + n0 + tn];
        }
        __syncthreads();
        // write: loop n, threads over k (256)
        for (int n = 0; n < 32; n++) {
            float inv = cinv[n];
            float x = tile[threadIdx.x][n];
            char q1, q0; quant2(x, inv, q1, q0);
            long di = (long)(n0 + n) * K + kc + threadIdx.x;
            dd1[di] = q1; dd0[di] = q0;
        }
        __syncthreads();
    }
}

// ---------- row quantizer for fp32 activation rows ----------
template<int KROW>
__global__ __launch_bounds__(256)
void rowquant(const float* __restrict__ src, char* d1, char* d0, float* sc)
{
    __shared__ float red[8]; __shared__ float sinv;
    long r = blockIdx.x;
    const float* s = src + r * KROW;
    float m = 0.f;
    for (int u = threadIdx.x; u < KROW; u += 256) m = fmaxf(m, fabsf(s[u]));
    m = warpMax(m);
    int wid = threadIdx.x >> 5, lane = threadIdx.x & 31;
    if (lane == 0) red[wid] = m;
    __syncthreads();
    if (threadIdx.x == 0) {
        float mm = 0.f;
        #pragma unroll
        for (int i = 0; i < 8; i++) mm = fmaxf(mm, red[i]);
        sc[r] = (mm > 0.f) ? (mm / 127.f) : 1e-30f;
        sinv = (mm > 0.f) ? (127.f / mm) : 0.f;
    }
    __syncthreads();
    float inv = sinv;
    for (int u = threadIdx.x; u < KROW; u += 256) {
        char q1, q0; quant2(s[u], inv, q1, q0);
        d1[r * KROW + u] = q1; d0[r * KROW + u] = q0;
    }
}

// ---------- combKV: sum 2 partials, quantize kv row ----------
__global__ __launch_bounds__(256)
void combKV(const float* __restrict__ mo, char* d1, char* d0, float* sc)
{
    __shared__ float row[768];
    __shared__ float red[8]; __shared__ float sinv;
    int r = blockIdx.x;              // 0..1535
    int zB = r / 768, rl = r % 768;
    long base = (long)(zB * 2) * UU + (long)rl * 768;
    float m = 0.f;
    for (int u = threadIdx.x; u < 768; u += 256) {
        float v = mo[base + u] + mo[base + UU + u];
        row[u] = v;
        m = fmaxf(m, fabsf(v));
    }
    m = warpMax(m);
    int wid = threadIdx.x >> 5, lane = threadIdx.x & 31;
    if (lane == 0) red[wid] = m;
    __syncthreads();
    if (threadIdx.x == 0) {
        float mm = 0.f;
        #pragma unroll
        for (int i = 0; i < 8; i++) mm = fmaxf(mm, red[i]);
        sc[r] = (mm > 0.f) ? (mm / 127.f) : 1e-30f;
        sinv = (mm > 0.f) ? (127.f / mm) : 0.f;
    }
    __syncthreads();
    float inv = sinv;
    for (int u = threadIdx.x; u < 768; u += 256) {
        char q1, q0; quant2(row[u], inv, q1, q0);
        d1[(long)r * 768 + u] = q1; d0[(long)r * 768 + u] = q0;
    }
}

// ---------- combF1: sum 3 partials + bias, sigmoid, quantize ----------
__global__ __launch_bounds__(256)
void combF1(const float* __restrict__ mo, const float* __restrict__ bias,
            char* d1, char* d0, float* sc)
{
    __shared__ float row[768];
    __shared__ float red[8]; __shared__ float sinv;
    int r = blockIdx.x;
    long base = (long)r * 768;
    float m = 0.f;
    for (int u = threadIdx.x; u < 768; u += 256) {
        float v = mo[base + u] + mo[base + HN + u] + mo[base + 2*HN + u];
        float t = v + __ldg(&bias[u]);
        float o = 1.f / (1.f + __expf(-t));
        row[u] = o;
        m = fmaxf(m, fabsf(o));
    }
    m = warpMax(m);
    int wid = threadIdx.x >> 5, lane = threadIdx.x & 31;
    if (lane == 0) red[wid] = m;
    __syncthreads();
    if (threadIdx.x == 0) {
        float mm = 0.f;
        #pragma unroll
        for (int i = 0; i < 8; i++) mm = fmaxf(mm, red[i]);
        sc[r] = (mm > 0.f) ? (mm / 127.f) : 1e-30f;
        sinv = (mm > 0.f) ? (127.f / mm) : 0.f;
    }
    __syncthreads();
    float inv = sinv;
    for (int u = threadIdx.x; u < 768; u += 256) {
        char q1, q0; quant2(row[u], inv, q1, q0);
        d1[base + u] = q1; d0[base + u] = q0;
    }
}

// ---------- combA: row combine + RMS (+gate/am-quant, or n-quant) ----------
// MODE 0: attn -> gate + quantized gated am ; MODE 1: moe -> hM + n quant
// MODE 2: ffn2 -> h, n fp32, n quant
template<int MODE>
__global__ __launch_bounds__(256)
void combA(const float* __restrict__ mo, const float* __restrict__ den,
           const float* __restrict__ hOld, const float* __restrict__ hMin,
           const float* __restrict__ bias, const float* __restrict__ eb,
           const float* __restrict__ gWl, const float* __restrict__ gbl,
           const float* __restrict__ gateIn,
           float* hMout, float* hOut, float* nOut, float* gateOut,
           char* n1, char* n0, float* sn,
           char* am1, char* am0, float* sam)
{
    __shared__ float row[768];
    __shared__ float red[8], redm[8]; __shared__ float rsh, rmx; __shared__ float gsl[8][8];
    __shared__ float gfin[8]; __shared__ float gmaxs;
    int r = blockIdx.x, tid = threadIdx.x;
    int wid = tid >> 5, lane = tid & 31;
    int b = r >> 10, t = r & 1023;
    for (int u = tid; u < 768; u += 256) {
        float v;
        if (MODE == 0) {
            long base = (long)(b * 3) * TU + (long)t * 768 + u;
            v = mo[base] + mo[base + TU] + mo[base + 2 * TU];
            v = v / den[r] + hOld[(long)r * 768 + u];
        } else {
            long base = (long)r * 768 + u;
            v = mo[base] + mo[base + HN] + mo[base + 2 * HN];
            if (MODE == 1) {
                float bm = 0.f;
                #pragma unroll
                for (int e = 0; e < 8; e++)
                    bm = fmaf(gateIn[(long)r * 8 + e], __ldg(&eb[e * 768 + u]), bm);
                v += bm;
                hMout[base] = v;
            } else {
                float tt = v + __ldg(&bias[u]);
                v = 1.f / (1.f + __expf(-tt)) + hMin[base] + hOld[base];
                hOut[base] = v;
            }
        }
        row[u] = v;
    }
    __syncthreads();
    float s = 0.f, m = 0.f;
    for (int u = tid; u < 768; u += 256) { float x = row[u]; s = fmaf(x, x, s); m = fmaxf(m, fabsf(x)); }
    s = warpSum(s); m = warpMax(m);
    if (lane == 0) { red[wid] = s; redm[wid] = m; }
    __syncthreads();
    if (tid == 0) {
        float tot = 0.f, mm = 0.f;
        #pragma unroll
        for (int i = 0; i < 8; i++) { tot += red[i]; mm = fmaxf(mm, redm[i]); }
        rsh = rsqrtf(tot / 768.f + EPS_F);
        rmx = mm;
    }
    __syncthreads();
    float rr = rsh;
    if (MODE != 0) {
        float mm = rmx * rr;
        if (tid == 0) sn[r] = (mm > 0.f) ? (mm / 127.f) : 1e-30f;
        float inv = (mm > 0.f) ? (127.f / mm) : 0.f;
        for (int u = tid; u < 768; u += 256) {
            float o = row[u] * rr;
            if (MODE == 2) nOut[(long)r * 768 + u] = o;
            char q1, q0; quant2(o, inv, q1, q0);
            n1[(long)r * 768 + u] = q1; n0[(long)r * 768 + u] = q0;
        }
        return;
    }
    // MODE 0: gate softmax, then quantized gated am
    float ge[8];
    #pragma unroll
    for (int e = 0; e < 8; e++) ge[e] = 0.f;
    for (int u = tid; u < 768; u += 256) {
        float o = row[u] * rr;
        #pragma unroll
        for (int e = 0; e < 8; e++) ge[e] = fmaf(o, __ldg(&gWl[u * 8 + e]), ge[e]);
    }
    #pragma unroll
    for (int e = 0; e < 8; e++) ge[e] = warpSum(ge[e]);
    if (lane < 8) gsl[wid][lane] = ge[lane];
    __syncthreads();
    if (tid == 0) {
        float sl[8];
        #pragma unroll
        for (int e = 0; e < 8; e++) {
            float tt = gbl[e];
            #pragma unroll
            for (int w = 0; w < 8; w++) tt += gsl[w][e];
            sl[e] = tt;
        }
        float mx = sl[0];
        #pragma unroll
        for (int e = 1; e < 8; e++) mx = fmaxf(mx, sl[e]);
        float ex[8], sum = 0.f;
        #pragma unroll
        for (int e = 0; e < 8; e++) { ex[e] = __expf(sl[e] - mx); sum += ex[e]; }
        float inv = 1.f / sum;
        float gm = 0.f;
        #pragma unroll
        for (int e = 0; e < 8; e++) {
            float gv = ex[e] * inv; gfin[e] = gv; gateOut[(long)r * 8 + e] = gv;
            gm = fmaxf(gm, gv);
        }
        gmaxs = gm;
        float mm = rmx * rsh * gm;
        sam[r] = (mm > 0.f) ? (mm / 127.f) : 1e-30f;
    }
    __syncthreads();
    float mm = rmx * rr * gmaxs;
    float inv = (mm > 0.f) ? (127.f / mm) : 0.f;
    long abase = (long)r * 6144;
    for (int i = tid; i < 6144; i += 256) {
        int e = i / 768, u = i % 768;
        float o = row[u] * rr * gfin[e];
        char q1, q0; quant2(o, inv, q1, q0);
        am1[abase + i] = q1; am0[abase + i] = q0;
    }
}

// ---------- small kernels ----------
__global__ __launch_bounds__(256)
void gatherq(const int* __restrict__ x, const float* __restrict__ emb,
             char* d1, char* d0, float* sc)
{
    __shared__ float row[768];
    __shared__ float red[8]; __shared__ float sinv;
    int r = blockIdx.x, tok = x[r];
    const float* s = emb + (long)tok * U_DIM;
    float m = 0.f;
    for (int u = threadIdx.x; u < 768; u += 256) { float v = s[u]; row[u] = v; m = fmaxf(m, fabsf(v)); }
    m = warpMax(m);
    int wid = threadIdx.x >> 5, lane = threadIdx.x & 31;
    if (lane == 0) red[wid] = m;
    __syncthreads();
    if (threadIdx.x == 0) {
        float mm = 0.f;
        #pragma unroll
        for (int i = 0; i < 8; i++) mm = fmaxf(mm, red[i]);
        sc[r] = (mm > 0.f) ? (mm / 127.f) : 1e-30f;
        sinv = (mm > 0.f) ? (127.f / mm) : 0.f;
    }
    __syncthreads();
    float inv = sinv;
    for (int u = threadIdx.x; u < 768; u += 256) {
        char q1, q0; quant2(row[u], inv, q1, q0);
        d1[(long)r * 768 + u] = q1; d0[(long)r * 768 + u] = q0;
    }
}

__global__ __launch_bounds__(256)
void rmsq(const float* __restrict__ h, char* d1, char* d0, float* sc)
{
    __shared__ float red[8], redm[8]; __shared__ float rsh, sinv;
    long r = blockIdx.x;
    const float* hr = h + r * U_DIM;
    float s = 0.f, m = 0.f;
    for (int u = threadIdx.x; u < U_DIM; u += 256) { float t = hr[u]; s = fmaf(t, t, s); m = fmaxf(m, fabsf(t)); }
    s = warpSum(s); m = warpMax(m);
    int wid = threadIdx.x >> 5, lane = threadIdx.x & 31;
    if (lane == 0) { red[wid] = s; redm[wid] = m; }
    __syncthreads();
    if (threadIdx.x == 0) {
        float tot = 0.f, mm = 0.f;
        #pragma unroll
        for (int i = 0; i < 8; i++) { tot += red[i]; mm = fmaxf(mm, redm[i]); }
        float rr = rsqrtf(tot / (float)U_DIM + EPS_F);
        rsh = rr;
        float mx = mm * rr;
        sc[r] = (mx > 0.f) ? (mx / 127.f) : 1e-30f;
        sinv = (mx > 0.f) ? (127.f / mx) : 0.f;
    }
    __syncthreads();
    float rr = rsh, inv = sinv;
    for (int u = threadIdx.x; u < U_DIM; u += 256) {
        char q1, q0; quant2(hr[u] * rr, inv, q1, q0);
        d1[r * U_DIM + u] = q1; d0[r * U_DIM + u] = q0;
    }
}

__global__ __launch_bounds__(256)
void colsum(const float* __restrict__ ktf, float* ks)
{
    int gw = blockIdx.x * 8 + (threadIdx.x >> 5);
    int lane = threadIdx.x & 31;
    const float* p = ktf + (long)gw * 1024;
    float s = 0.f;
    for (int t = lane; t < 1024; t += 32) s += p[t];
    s = warpSum(s);
    if (lane == 0) ks[gw] = s;
}
__global__ __launch_bounds__(256)
void denk(const float* __restrict__ qf, const float* __restrict__ ks, float* den)
{
    int gw = (blockIdx.x * 256 + threadIdx.x) >> 5;
    int lane = threadIdx.x & 31;
    if (gw >= BT) return;
    int b = gw >> 10;
    const float* qr = qf + (long)gw * U_DIM;
    const float* kb = ks + b * U_DIM;
    float s = 0.f;
    for (int u = lane; u < U_DIM; u += 32) s = fmaf(qr[u], kb[u], s);
    s = warpSum(s);
    if (lane == 0) den[gw] = s + EPS_F;
}
__global__ __launch_bounds__(256)
void addk(const float* __restrict__ a, const float* __restrict__ b, float* c, int n)
{
    int i = blockIdx.x * 256 + threadIdx.x;
    if (i < n) c[i] = a[i] + b[i];
}

// ---------- host ----------
static void tc(int epi, GArgs& a, int M, int N, int Z)
{
    dim3 g(N / 128, M / 128, Z);
    switch (epi) {
    case 1: mma_gemm<1><<<g, 256, DSM>>>(a); break;
    case 2: mma_gemm<2><<<g, 256, DSM>>>(a); break;
    case 7: mma_gemm<7><<<g, 256, DSM>>>(a); break;
    case 8: mma_gemm<8><<<g, 256, DSM>>>(a); break;
    }
}

extern "C" void kernel_launch(void* const* d_in, const int* in_sizes, int n_in,
                              void* d_out, int out_size)
{
    const int*   x    = (const int*)  d_in[0];
    const float* emb  = (const float*)d_in[1];
    const float* W_in = (const float*)d_in[2];
    const float* Wq   = (const float*)d_in[3];
    const float* bq   = (const float*)d_in[4];
    const float* Wk   = (const float*)d_in[5];
    const float* bk   = (const float*)d_in[6];
    const float* Wv   = (const float*)d_in[7];
    const float* bv   = (const float*)d_in[8];
    const float* gW   = (const float*)d_in[9];
    const float* gb   = (const float*)d_in[10];
    const float* eW   = (const float*)d_in[11];
    const float* eb   = (const float*)d_in[12];
    const float* fW1  = (const float*)d_in[13];
    const float* fb1  = (const float*)d_in[14];
    const float* fW2  = (const float*)d_in[15];
    const float* fb2  = (const float*)d_in[16];
    const float* Wlog = (const float*)d_in[17];
    float* out = (float*)d_out;

    cudaFuncSetAttribute((const void*)mma_gemm<1>, cudaFuncAttributeMaxDynamicSharedMemorySize, DSM);
    cudaFuncSetAttribute((const void*)mma_gemm<2>, cudaFuncAttributeMaxDynamicSharedMemorySize, DSM);
    cudaFuncSetAttribute((const void*)mma_gemm<7>, cudaFuncAttributeMaxDynamicSharedMemorySize, DSM);
    cudaFuncSetAttribute((const void*)mma_gemm<8>, cudaFuncAttributeMaxDynamicSharedMemorySize, DSM);

    char *w1, *w0, *n1, *n0, *x1, *x0, *q1, *q0, *kt1, *kt0, *vt1, *vt0;
    char *kv1, *kv0, *f11, *f10, *am1, *am0;
    float *wsc, *h, *h0, *hA, *hM, *n, *mo, *qf, *ktf, *vtf, *ksum, *den, *gate;
    float *sn, *sx, *sq, *skt, *svt, *skv, *sf1, *sam;
    cudaGetSymbolAddress((void**)&w1, g_w1);    cudaGetSymbolAddress((void**)&w0, g_w0);
    cudaGetSymbolAddress((void**)&wsc, g_wsc);
    cudaGetSymbolAddress((void**)&h, g_h);      cudaGetSymbolAddress((void**)&h0, g_h0);
    cudaGetSymbolAddress((void**)&hA, g_hA);    cudaGetSymbolAddress((void**)&hM, g_hM);
    cudaGetSymbolAddress((void**)&n, g_n);      cudaGetSymbolAddress((void**)&mo, g_mo);
    cudaGetSymbolAddress((void**)&qf, g_qf);    cudaGetSymbolAddress((void**)&ktf, g_ktf);
    cudaGetSymbolAddress((void**)&vtf, g_vtf);  cudaGetSymbolAddress((void**)&ksum, g_ksum);
    cudaGetSymbolAddress((void**)&den, g_den);  cudaGetSymbolAddress((void**)&gate, g_gate);
    cudaGetSymbolAddress((void**)&n1, g_n1);    cudaGetSymbolAddress((void**)&n0, g_n0);
    cudaGetSymbolAddress((void**)&x1, g_x1);    cudaGetSymbolAddress((void**)&x0, g_x0);
    cudaGetSymbolAddress((void**)&q1, g_q1);    cudaGetSymbolAddress((void**)&q0, g_q0);
    cudaGetSymbolAddress((void**)&kt1, g_kt1);  cudaGetSymbolAddress((void**)&kt0, g_kt0);
    cudaGetSymbolAddress((void**)&vt1, g_vt1);  cudaGetSymbolAddress((void**)&vt0, g_vt0);
    cudaGetSymbolAddress((void**)&kv1, g_kv1);  cudaGetSymbolAddress((void**)&kv0, g_kv0);
    cudaGetSymbolAddress((void**)&f11, g_f11);  cudaGetSymbolAddress((void**)&f10, g_f10);
    cudaGetSymbolAddress((void**)&am1, g_am1);  cudaGetSymbolAddress((void**)&am0, g_am0);
    cudaGetSymbolAddress((void**)&sn, g_sn);    cudaGetSymbolAddress((void**)&sx, g_sx);
    cudaGetSymbolAddress((void**)&sq, g_sq);    cudaGetSymbolAddress((void**)&skt, g_skt);
    cudaGetSymbolAddress((void**)&svt, g_svt);  cudaGetSymbolAddress((void**)&skv, g_skv);
    cudaGetSymbolAddress((void**)&sf1, g_sf1);  cudaGetSymbolAddress((void**)&sam, g_sam);

    GArgs a;
    // ncu -s lands on 0-based launch #3 -> h0 GEMM
    wquant<<<dim3(24, 1, 1),  256>>>(W_in, w1 + OFF_WIN, w0 + OFF_WIN, wsc + SC_WIN, 768, 768, 0, 0, 0);     // 0
    gatherq<<<BT, 256>>>(x, emb, x1, x0, sx);                                                                 // 1
    wquant<<<dim3(24, 1, 16), 256>>>(Wq, w1 + OFF_QKV, w0 + OFF_QKV, wsc + SC_QKV, 768, 768, UU, 3*UU, 2304); // 2
    a = {}; a.A1 = x1; a.A0 = x0; a.B1 = w1 + OFF_WIN; a.B0 = w0 + OFF_WIN;
    a.sA = sx; a.sB = wsc + SC_WIN; a.N = 768; a.K = 768; a.SK = 1;
    a.outF = h0; a.outF2 = h;
    tc(1, a, BT, 768, 1);                                                                                     // 3
    wquant<<<dim3(24, 1, 16), 256>>>(Wk, w1 + OFF_QKV + UU, w0 + OFF_QKV + UU, wsc + SC_QKV + 768, 768, 768, UU, 3*UU, 2304);
    wquant<<<dim3(24, 1, 16), 256>>>(Wv, w1 + OFF_QKV + 2*UU, w0 + OFF_QKV + 2*UU, wsc + SC_QKV + 1536, 768, 768, UU, 3*UU, 2304);
    wquant<<<dim3(24, 1, 16), 256>>>(fW1, w1 + OFF_F1, w0 + OFF_F1, wsc + SC_F1, 768, 768, UU, UU, 768);
    wquant<<<dim3(24, 1, 16), 256>>>(fW2, w1 + OFF_F2, w0 + OFF_F2, wsc + SC_F2, 768, 768, UU, UU, 768);
    wquant<<<dim3(24, 1, 16), 256>>>(eW, w1 + OFF_EW, w0 + OFF_EW, wsc + SC_EW, 6144, 768, 8*UU, 8*UU, 768);
    wquant<<<dim3(1000, 1, 1), 256>>>(Wlog, w1 + OFF_WLOG, w0 + OFF_WLOG, wsc + SC_WLOG, 768, 32000, 0, 0, 0);
    rmsq<<<BT, 256>>>(h, n1, n0, sn);

    for (int l = 0; l < L_DIM; l++) {
        // qkv: A=n, B=qkv rows; writes qf (phi), ktf, vtf
        a = {}; a.A1 = n1; a.A0 = n0;
        a.B1 = w1 + OFF_QKV + (long)l * 3 * UU; a.B0 = w0 + OFF_QKV + (long)l * 3 * UU;
        a.sA = sn; a.sB = wsc + SC_QKV + (long)l * 2304;
        a.N = 2304; a.K = 768; a.SK = 1;
        a.bias = bq + l * U_DIM; a.bias2 = bk + l * U_DIM; a.bias3 = bv + l * U_DIM;
        a.qf = qf; a.ktf = ktf; a.vtf = vtf;
        tc(8, a, BT, 2304, 1);
        rowquant<768><<<BT, 256>>>(qf, q1, q0, sq);
        rowquant<1024><<<1536, 256>>>(ktf, kt1, kt0, skt);
        rowquant<1024><<<1536, 256>>>(vtf, vt1, vt0, svt);
        colsum<<<192, 256>>>(ktf, ksum);
        denk<<<256, 256>>>(qf, ksum, den);
        // kvT = vT kT^T
        a = {}; a.A1 = vt1; a.A0 = vt0; a.B1 = kt1; a.B0 = kt0;
        a.sA = svt; a.sB = skt; a.saZ = 768; a.sbZ = 768;
        a.N = 768; a.K = 1024; a.kSplit = 512; a.SK = 2; a.aZ = TU; a.bZ = TU; a.cZ = UU;
        a.outF = mo;
        tc(2, a, 768, 768, 4);
        combKV<<<1536, 256>>>(mo, kv1, kv0, skv);
        // attn = q @ kv
        a = {}; a.A1 = q1; a.A0 = q0; a.B1 = kv1; a.B0 = kv0;
        a.sA = sq; a.sB = skv; a.saZ = 1024; a.sbZ = 768;
        a.N = 768; a.K = 768; a.kSplit = 256; a.SK = 3; a.aZ = TU; a.bZ = UU; a.cZ = TU;
        a.outF = mo;
        tc(2, a, T_DIM, 768, 6);
        combA<0><<<BT, 256>>>(mo, den, h, nullptr, nullptr, nullptr,
                              gW + (long)l * U_DIM * E_DIM, gb + l * E_DIM, nullptr,
                              nullptr, nullptr, nullptr, gate,
                              nullptr, nullptr, nullptr, am1, am0, sam);
        // moe
        a = {}; a.A1 = am1; a.A0 = am0;
        a.B1 = w1 + OFF_EW + (long)l * 8 * UU; a.B0 = w0 + OFF_EW + (long)l * 8 * UU;
        a.sA = sam; a.sB = wsc + SC_EW + (long)l * 768;
        a.N = 768; a.K = 6144; a.kSplit = 2048; a.SK = 3; a.cZ = HN; a.outF = mo;
        tc(2, a, BT, 768, 3);
        combA<1><<<BT, 256>>>(mo, nullptr, nullptr, nullptr, nullptr,
                              eb + (long)l * E_DIM * U_DIM, nullptr, nullptr, gate,
                              hM, nullptr, nullptr, nullptr,
                              n1, n0, sn, nullptr, nullptr, nullptr);
        // ffn
        a = {}; a.A1 = n1; a.A0 = n0;
        a.B1 = w1 + OFF_F1 + (long)l * UU; a.B0 = w0 + OFF_F1 + (long)l * UU;
        a.sA = sn; a.sB = wsc + SC_F1 + (long)l * 768;
        a.N = 768; a.K = 768; a.kSplit = 256; a.SK = 3; a.cZ = HN; a.outF = mo;
        tc(2, a, BT, 768, 3);
        combF1<<<BT, 256>>>(mo, fb1 + l * U_DIM, f11, f10, sf1);
        a = {}; a.A1 = f11; a.A0 = f10;
        a.B1 = w1 + OFF_F2 + (long)l * UU; a.B0 = w0 + OFF_F2 + (long)l * UU;
        a.sA = sf1; a.sB = wsc + SC_F2 + (long)l * 768;
        a.N = 768; a.K = 768; a.kSplit = 256; a.SK = 3; a.cZ = HN; a.outF = mo;
        tc(2, a, BT, 768, 3);
        combA<2><<<BT, 256>>>(mo, nullptr, h, hM, fb2 + l * U_DIM, nullptr,
                              nullptr, nullptr, nullptr,
                              nullptr, h, n, nullptr,
                              n1, n0, sn, nullptr, nullptr, nullptr);
    }

    // final: n = rms(h) (fp32 from combA<2>); hA = n + h0; quantize rms(hA); logits
    addk<<<(int)(HN/256), 256>>>(n, h0, hA, (int)HN);
    rmsq<<<BT, 256>>>(hA, n1, n0, sn);
    a = {}; a.A1 = n1; a.A0 = n0; a.B1 = w1 + OFF_WLOG; a.B0 = w0 + OFF_WLOG;
    a.sA = sn; a.sB = wsc + SC_WLOG;
    a.N = 32000; a.K = 768; a.SK = 1; a.outF = out;
    tc(7, a, BT, 32000, 1);
}

// round 14
// speedup vs baseline: 2.3704x; 2.3704x over previous
#include <cuda_runtime.h>
#include <cuda_bf16.h>
#include <cuda_fp16.h>
#include <cstdint>

#define U_DIM 768
#define T_DIM 1024
#define B_DIM 2
#define BT    2048
#define E_DIM 8
#define L_DIM 16
#define V_DIM 32000
#define EPS_F 1e-6f
#define UU    589824L
#define TU    786432L
#define HN    1572864L

#define OFF_WIN  0L
#define OFF_QKV  (UU)
#define OFF_F1   (OFF_QKV + 48L*UU)
#define OFF_F2   (OFF_F1 + 16L*UU)
#define OFF_EW   (OFF_F2 + 16L*UU)
#define OFF_WLOG (OFF_EW + 128L*UU)
#define W_TOTAL  (OFF_WLOG + 32000L*768L)

typedef __nv_bfloat16 bf16;

__device__ bf16 g_whi[W_TOTAL];
__device__ bf16 g_wlo[W_TOTAL];
__device__ float g_h[HN], g_h0[HN], g_hA[HN], g_hM[HN], g_n[HN];
__device__ float g_mo[3*HN];
__device__ float g_ksum[B_DIM*U_DIM], g_den[BT], g_gate[BT*E_DIM];
__device__ bf16 g_nhi[HN],  g_nlo[HN];
__device__ bf16 g_xhi[HN],  g_xlo[HN];
__device__ bf16 g_qhi[HN],  g_qlo[HN];
__device__ bf16 g_kthi[HN], g_ktlo[HN];
__device__ bf16 g_vthi[HN], g_vtlo[HN];
__device__ bf16 g_kvhi[B_DIM*UU], g_kvlo[B_DIM*UU];
__device__ bf16 g_f1hi[HN], g_f1lo[HN];
__device__ bf16 g_amhi[BT*6144L], g_amlo[BT*6144L];

__device__ __forceinline__ uint32_t smem_u32(const void* p) {
    uint32_t a;
    asm("{ .reg .u64 t; cvta.to.shared.u64 t, %1; cvt.u32.u64 %0, t; }" : "=r"(a) : "l"(p));
    return a;
}
__device__ __forceinline__ void split2(float x, bf16& hi, bf16& lo) {
    hi = __float2bfloat16(x);
    lo = __float2bfloat16(x - __bfloat162float(hi));
}
__device__ __forceinline__ void split2h(float x, __half& hi, __half& lo) {
    hi = __float2half(x);
    lo = __float2half(x - __half2float(hi));
}
__device__ __forceinline__ float warpSum(float v) {
    #pragma unroll
    for (int o = 16; o > 0; o >>= 1) v += __shfl_xor_sync(0xffffffffu, v, o);
    return v;
}

struct GArgs {
    const bf16 *Ahi, *Alo, *Bhi, *Blo;
    int N, K, kSplit, SK;
    long aZ, bZ, cZ;
    const float *bias, *bias2, *bias3;
    float *outF, *outF2;
    bf16 *oHi, *oLo, *oHi2, *oLo2, *oHi3, *oLo3;
    float *ksum;
};

#define ROWS 72
#define TB   (128 * ROWS * 2)
#define DSM  (12 * TB)         // 3 stages x 4 tiles = 221184

#define MMA_BF(dv, afv, bfv) \
    asm volatile("mma.sync.aligned.m16n8k16.row.col.f32.bf16.bf16.f32 " \
        "{%0,%1,%2,%3}, {%4,%5,%6,%7}, {%8,%9}, {%0,%1,%2,%3};" \
        : "+f"((dv)[0]), "+f"((dv)[1]), "+f"((dv)[2]), "+f"((dv)[3]) \
        : "r"((afv)[0]), "r"((afv)[1]), "r"((afv)[2]), "r"((afv)[3]), \
          "r"((bfv)[0]), "r"((bfv)[1]))
#define MMA_F16(dv, afv, bfv) \
    asm volatile("mma.sync.aligned.m16n8k16.row.col.f32.f16.f16.f32 " \
        "{%0,%1,%2,%3}, {%4,%5,%6,%7}, {%8,%9}, {%0,%1,%2,%3};" \
        : "+f"((dv)[0]), "+f"((dv)[1]), "+f"((dv)[2]), "+f"((dv)[3]) \
        : "r"((afv)[0]), "r"((afv)[1]), "r"((afv)[2]), "r"((afv)[3]), \
          "r"((bfv)[0]), "r"((bfv)[1]))

// EPI: 1 out(+copy), 2 partial, 7 logits x2, 8 qkv
// PM: 0 = bf16 3-pass, 1 = fp16 2-pass, 2 = fp16 3-pass
template<int EPI, int PM>
__global__ __launch_bounds__(256)
void mma_gemm(GArgs g)
{
    extern __shared__ char smem[];
    uint32_t sb = smem_u32(smem);
    const int tid = threadIdx.x, wid = tid >> 5, lane = tid & 31;
    const int wm = wid >> 2, wn = wid & 3;
    const int z = blockIdx.z;
    const int zB = g.SK > 1 ? z / g.SK : z;
    const int zS = g.SK > 1 ? z % g.SK : 0;
    const int row0 = blockIdx.y * 128, col0 = blockIdx.x * 128;
    const int Nn = g.N, K = g.K;

    const bf16* Ahi = g.Ahi + (long)zB * g.aZ;
    const bf16* Alo = g.Alo + (long)zB * g.aZ;
    const bf16* Bhi = g.Bhi + (long)zB * g.bZ;
    const bf16* Blo = g.Blo + (long)zB * g.bZ;
    const int kbase = g.kSplit ? zS * g.kSplit : 0;
    const int CH = (g.kSplit ? g.kSplit : K) >> 6;

    float d[4][4][4];
    #pragma unroll
    for (int a = 0; a < 4; a++)
        #pragma unroll
        for (int b = 0; b < 4; b++)
            #pragma unroll
            for (int c = 0; c < 4; c++) d[a][b][c] = 0.f;

    auto issue = [&](int c, int s) {
        int k0 = kbase + (c << 6);
        const bf16* srcs[4] = {
            Ahi + (long)row0 * K + k0, Alo + (long)row0 * K + k0,
            Bhi + (long)col0 * K + k0, Blo + (long)col0 * K + k0 };
        #pragma unroll
        for (int t = 0; t < 4; t++) {
            if (PM == 1 && t == 1) continue;
            uint32_t dst = sb + (uint32_t)(s * 4 + t) * TB;
            #pragma unroll
            for (int i = 0; i < 4; i++) {
                int idx = tid + (i << 8);
                int r = idx >> 3, cc = idx & 7;
                uint32_t doff = (uint32_t)(r * ROWS + cc * 8) * 2;
                const void* sp = srcs[t] + (long)r * K + cc * 8;
                asm volatile("cp.async.cg.shared.global [%0], [%1], 16;"
                             :: "r"(dst + doff), "l"(sp));
            }
        }
        asm volatile("cp.async.commit_group;");
    };

    issue(0, 0);
    if (CH > 1) issue(1, 1);
    for (int c = 0; c < CH; c++) {
        int s = c % 3;
        if (c + 2 < CH) { issue(c + 2, (c + 2) % 3); asm volatile("cp.async.wait_group 2;"); }
        else if (c + 1 < CH) { asm volatile("cp.async.wait_group 1;"); }
        else { asm volatile("cp.async.wait_group 0;"); }
        __syncthreads();
        uint32_t bAH = sb + (uint32_t)(s * 4 + 0) * TB;
        uint32_t bAL = sb + (uint32_t)(s * 4 + 1) * TB;
        uint32_t bBH = sb + (uint32_t)(s * 4 + 2) * TB;
        uint32_t bBL = sb + (uint32_t)(s * 4 + 3) * TB;
        #pragma unroll
        for (int ks = 0; ks < 4; ks++) {
            int k16 = ks * 16;
            int aoff = (wm * 64 + (lane & 15)) * ROWS + k16 + ((lane >> 4) << 3);
            int boff = (wn * 32 + (lane & 7)) * ROWS + k16 + (((lane >> 3) & 1) << 3);
            uint32_t af[4][4], af2[4][4], bf_[4][2];
            #pragma unroll
            for (int mt = 0; mt < 4; mt++) {
                uint32_t ad = bAH + (uint32_t)(aoff + mt * 16 * ROWS) * 2;
                asm volatile("ldmatrix.sync.aligned.m8n8.x4.shared.b16 {%0,%1,%2,%3}, [%4];"
                    : "=r"(af[mt][0]), "=r"(af[mt][1]), "=r"(af[mt][2]), "=r"(af[mt][3]) : "r"(ad));
            }
            #pragma unroll
            for (int nt = 0; nt < 4; nt++) {
                uint32_t bd = bBH + (uint32_t)(boff + nt * 8 * ROWS) * 2;
                asm volatile("ldmatrix.sync.aligned.m8n8.x2.shared.b16 {%0,%1}, [%2];"
                    : "=r"(bf_[nt][0]), "=r"(bf_[nt][1]) : "r"(bd));
            }
            #pragma unroll
            for (int mt = 0; mt < 4; mt++)
                #pragma unroll
                for (int nt = 0; nt < 4; nt++) {
                    if (PM) { MMA_F16(d[mt][nt], af[mt], bf_[nt]); }
                    else    { MMA_BF (d[mt][nt], af[mt], bf_[nt]); }
                }
            if (PM != 1) {
                #pragma unroll
                for (int mt = 0; mt < 4; mt++) {
                    uint32_t ad = bAL + (uint32_t)(aoff + mt * 16 * ROWS) * 2;
                    asm volatile("ldmatrix.sync.aligned.m8n8.x4.shared.b16 {%0,%1,%2,%3}, [%4];"
                        : "=r"(af2[mt][0]), "=r"(af2[mt][1]), "=r"(af2[mt][2]), "=r"(af2[mt][3]) : "r"(ad));
                }
                #pragma unroll
                for (int mt = 0; mt < 4; mt++)
                    #pragma unroll
                    for (int nt = 0; nt < 4; nt++) {
                        if (PM) { MMA_F16(d[mt][nt], af2[mt], bf_[nt]); }
                        else    { MMA_BF (d[mt][nt], af2[mt], bf_[nt]); }
                    }
            }
            #pragma unroll
            for (int nt = 0; nt < 4; nt++) {
                uint32_t bd = bBL + (uint32_t)(boff + nt * 8 * ROWS) * 2;
                asm volatile("ldmatrix.sync.aligned.m8n8.x2.shared.b16 {%0,%1}, [%2];"
                    : "=r"(bf_[nt][0]), "=r"(bf_[nt][1]) : "r"(bd));
            }
            #pragma unroll
            for (int mt = 0; mt < 4; mt++)
                #pragma unroll
                for (int nt = 0; nt < 4; nt++) {
                    if (PM) { MMA_F16(d[mt][nt], af[mt], bf_[nt]); }
                    else    { MMA_BF (d[mt][nt], af[mt], bf_[nt]); }
                }
        }
        __syncthreads();
    }

    // ---------------- epilogues ----------------
    if (EPI == 8) {
        const int blkN = col0 / 768;
        const int cc0  = col0 - blkN * 768;
        if (blkN == 0) {
            #pragma unroll
            for (int mt = 0; mt < 4; mt++)
                #pragma unroll
                for (int half = 0; half < 2; half++) {
                    int rg = row0 + wm * 64 + mt * 16 + (lane >> 2) + half * 8;
                    #pragma unroll
                    for (int nt = 0; nt < 4; nt++) {
                        int col = cc0 + wn * 32 + nt * 8 + 2 * (lane & 3);
                        float t0 = d[mt][nt][half*2+0] + __ldg(&g.bias[col]);
                        float t1 = d[mt][nt][half*2+1] + __ldg(&g.bias[col+1]);
                        float o0 = (t0 > 0.f) ? (t0 + 1.f) : __expf(t0);
                        float o1 = (t1 > 0.f) ? (t1 + 1.f) : __expf(t1);
                        bf16 h0b,l0b,h1b,l1b; split2(o0,h0b,l0b); split2(o1,h1b,l1b);
                        __nv_bfloat162 ph; ph.x=h0b; ph.y=h1b;
                        __nv_bfloat162 pl; pl.x=l0b; pl.y=l1b;
                        long idx = (long)rg * 768 + col;
                        *(__nv_bfloat162*)(g.oHi + idx) = ph;
                        *(__nv_bfloat162*)(g.oLo + idx) = pl;
                    }
                }
        } else {
            const float* bp = (blkN == 1) ? g.bias2 : g.bias3;
            float* tile = (float*)smem;
            #pragma unroll
            for (int mt = 0; mt < 4; mt++)
                #pragma unroll
                for (int nt = 0; nt < 4; nt++)
                    #pragma unroll
                    for (int half = 0; half < 2; half++)
                        #pragma unroll
                        for (int jj = 0; jj < 2; jj++) {
                            int r = wm*64 + mt*16 + (lane>>2) + half*8;
                            int cl = wn*32 + nt*8 + 2*(lane&3) + jj;
                            float t = d[mt][nt][half*2+jj] + __ldg(&bp[cc0 + cl]);
                            if (blkN == 1) t = (t > 0.f) ? (t + 1.f) : __expf(t);
                            tile[r * 130 + cl] = t;
                        }
            __syncthreads();
            bf16* dh = (blkN == 1) ? g.oHi2 : g.oHi3;
            bf16* dl = (blkN == 1) ? g.oLo2 : g.oLo3;
            int u_l = tid & 127, th = tid >> 7;
            int bb = row0 >> 10, t0 = row0 & 1023;
            long rowbase = ((long)(bb * 768 + cc0 + u_l)) * 1024 + t0 + th * 64;
            uint32_t hb[32], lb[32];
            float csum = 0.f;
            #pragma unroll
            for (int j = 0; j < 64; j += 2) {
                float v0 = tile[(th*64 + j) * 130 + u_l];
                float v1 = tile[(th*64 + j + 1) * 130 + u_l];
                if (blkN == 1) csum += v0 + v1;
                bf16 h0b,l0b,h1b,l1b; split2(v0,h0b,l0b); split2(v1,h1b,l1b);
                __nv_bfloat162 ph; ph.x=h0b; ph.y=h1b;
                __nv_bfloat162 pl; pl.x=l0b; pl.y=l1b;
                hb[j>>1] = *(uint32_t*)&ph; lb[j>>1] = *(uint32_t*)&pl;
            }
            uint4* dh4 = (uint4*)(dh + rowbase);
            uint4* dl4 = (uint4*)(dl + rowbase);
            #pragma unroll
            for (int i = 0; i < 8; i++) { dh4[i] = ((uint4*)hb)[i]; dl4[i] = ((uint4*)lb)[i]; }
            if (blkN == 1) atomicAdd(&g.ksum[bb * 768 + cc0 + u_l], csum);
        }
        return;
    }

    float* outF = g.outF + (long)z * g.cZ;
    #pragma unroll
    for (int mt = 0; mt < 4; mt++)
        #pragma unroll
        for (int half = 0; half < 2; half++) {
            int rg = row0 + wm * 64 + mt * 16 + (lane >> 2) + half * 8;
            #pragma unroll
            for (int nt = 0; nt < 4; nt++) {
                int col = col0 + wn * 32 + nt * 8 + 2 * (lane & 3);
                #pragma unroll
                for (int jj = 0; jj < 2; jj++) {
                    float x = d[mt][nt][half*2+jj];
                    long idx = (long)rg * Nn + col + jj;
                    if (EPI == 2) outF[idx] = x;
                    else if (EPI == 7) outF[idx] = x * 2.0f;
                    else { outF[idx] = x; if (g.outF2) g.outF2[idx] = x; }
                }
            }
        }
}

// ---------- row-fused combines ----------
template<int MODE>
__global__ __launch_bounds__(256)
void combA(const float* __restrict__ mo, const float* __restrict__ den,
           const float* __restrict__ hOld, const float* __restrict__ hMin,
           const float* __restrict__ bias, const float* __restrict__ eb,
           const float* __restrict__ gWl, const float* __restrict__ gbl,
           const float* __restrict__ gateIn,
           float* hMout, float* hOut, float* nOut, float* gateOut,
           bf16* nhi, bf16* nlo, bf16* amhi, bf16* amlo)
{
    __shared__ float row[768];
    __shared__ float red[8]; __shared__ float rsh; __shared__ float gsl[8][8];
    __shared__ float gfin[8];
    int r = blockIdx.x, tid = threadIdx.x;
    int wid = tid >> 5, lane = tid & 31;
    int b = r >> 10, t = r & 1023;
    for (int u = tid; u < 768; u += 256) {
        float v;
        if (MODE == 0) {
            long base = (long)(b * 3) * TU + (long)t * 768 + u;
            v = mo[base] + mo[base + TU] + mo[base + 2 * TU];
            v = v / den[r] + hOld[(long)r * 768 + u];
        } else {
            long base = (long)r * 768 + u;
            v = mo[base] + mo[base + HN] + mo[base + 2 * HN];
            if (MODE == 1) {
                float bm = 0.f;
                #pragma unroll
                for (int e = 0; e < 8; e++)
                    bm = fmaf(gateIn[(long)r * 8 + e], __ldg(&eb[e * 768 + u]), bm);
                v += bm;
                hMout[base] = v;
            } else {
                float tt = v + __ldg(&bias[u]);
                v = 1.f / (1.f + __expf(-tt)) + hMin[base] + hOld[base];
                hOut[base] = v;
            }
        }
        row[u] = v;
    }
    __syncthreads();
    float s = 0.f;
    for (int u = tid; u < 768; u += 256) { float x = row[u]; s = fmaf(x, x, s); }
    s = warpSum(s);
    if (lane == 0) red[wid] = s;
    __syncthreads();
    if (tid == 0) {
        float tot = 0.f;
        #pragma unroll
        for (int i = 0; i < 8; i++) tot += red[i];
        rsh = rsqrtf(tot / 768.f + EPS_F);
    }
    __syncthreads();
    float rr = rsh;
    if (MODE != 0) {
        for (int u = tid; u < 768; u += 256) {
            float o = row[u] * rr;
            if (MODE == 2) nOut[(long)r * 768 + u] = o;
            bf16 hi, lo; split2(o, hi, lo);
            nhi[(long)r * 768 + u] = hi; nlo[(long)r * 768 + u] = lo;
        }
        return;
    }
    float ge[8];
    #pragma unroll
    for (int e = 0; e < 8; e++) ge[e] = 0.f;
    for (int u = tid; u < 768; u += 256) {
        float o = row[u] * rr;
        #pragma unroll
        for (int e = 0; e < 8; e++) ge[e] = fmaf(o, __ldg(&gWl[u * 8 + e]), ge[e]);
    }
    #pragma unroll
    for (int e = 0; e < 8; e++) ge[e] = warpSum(ge[e]);
    if (lane < 8) gsl[wid][lane] = ge[lane];
    __syncthreads();
    if (tid == 0) {
        float sl[8];
        #pragma unroll
        for (int e = 0; e < 8; e++) {
            float tt = gbl[e];
            #pragma unroll
            for (int w = 0; w < 8; w++) tt += gsl[w][e];
            sl[e] = tt;
        }
        float mx = sl[0];
        #pragma unroll
        for (int e = 1; e < 8; e++) mx = fmaxf(mx, sl[e]);
        float ex[8], sum = 0.f;
        #pragma unroll
        for (int e = 0; e < 8; e++) { ex[e] = __expf(sl[e] - mx); sum += ex[e]; }
        float inv = 1.f / sum;
        #pragma unroll
        for (int e = 0; e < 8; e++) { float gv = ex[e] * inv; gfin[e] = gv; gateOut[(long)r * 8 + e] = gv; }
    }
    __syncthreads();
    long abase = (long)r * 6144;
    for (int i = tid; i < 3072; i += 256) {
        int e = i / 384, u2 = (i % 384) * 2;
        float gv = gfin[e];
        float o0 = row[u2] * rr * gv, o1 = row[u2 + 1] * rr * gv;
        bf16 h0b,l0b,h1b,l1b; split2(o0,h0b,l0b); split2(o1,h1b,l1b);
        __nv_bfloat162 ph; ph.x=h0b; ph.y=h1b;
        __nv_bfloat162 pl; pl.x=l0b; pl.y=l1b;
        *(__nv_bfloat162*)(amhi + abase + e * 768 + u2) = ph;
        *(__nv_bfloat162*)(amlo + abase + e * 768 + u2) = pl;
    }
}

template<int MODE>
__global__ __launch_bounds__(256)
void comb(const float* __restrict__ p, long segZ, int ns, long total,
          const float* __restrict__ bias, bf16* oHi, bf16* oLo)
{
    long i4 = ((long)blockIdx.x * 256 + threadIdx.x) * 4;
    if (i4 >= total) return;
    long base = (i4 / segZ) * (long)ns * segZ + (i4 % segZ);
    float4 s = *(const float4*)(p + base);
    float4 s1 = *(const float4*)(p + base + segZ);
    s.x += s1.x; s.y += s1.y; s.z += s1.z; s.w += s1.w;
    if (ns == 3) {
        float4 s2 = *(const float4*)(p + base + 2 * segZ);
        s.x += s2.x; s.y += s2.y; s.z += s2.z; s.w += s2.w;
    }
    float v[4] = {s.x, s.y, s.z, s.w};
    int col = (int)(i4 % 768);
    bf16 hh[4], ll[4];
    #pragma unroll
    for (int j = 0; j < 4; j++) {
        float o = v[j];
        if (MODE == 1) { float t = o + __ldg(&bias[col + j]); o = 1.f / (1.f + __expf(-t)); }
        split2(o, hh[j], ll[j]);
    }
    *(uint2*)(oHi + i4) = *(uint2*)hh;
    *(uint2*)(oLo + i4) = *(uint2*)ll;
}

// ---------- prepack ----------
__global__ __launch_bounds__(256)
void tsplit(const float* __restrict__ src, bf16* dhi, bf16* dlo, int K, int N,
            int mode, long outZ, long rowOff)
{
    __shared__ float t[32][33];
    int z = blockIdx.z;
    const float* s = src + (long)z * K * N;
    long dbase; int dld;
    if (mode == 1) { int l = z >> 3, e = z & 7; dbase = (long)l * 8 * UU + (long)e * U_DIM; dld = 6144; }
    else { dbase = (long)z * outZ + rowOff; dld = K; }
    int n0 = blockIdx.x * 32, k0 = blockIdx.y * 32;
    int tx = threadIdx.x & 31, ty = threadIdx.x >> 5;
    #pragma unroll
    for (int i = 0; i < 32; i += 8) t[ty + i][tx] = s[(long)(k0 + ty + i) * N + n0 + tx];
    __syncthreads();
    #pragma unroll
    for (int i = 0; i < 32; i += 8) {
        float v = t[tx][ty + i];
        long di = dbase + (long)(n0 + ty + i) * dld + k0 + tx;
        if (mode == 2) {
            __half hi, lo; split2h(v, hi, lo);
            ((__half*)dhi)[di] = hi; ((__half*)dlo)[di] = lo;
        } else {
            bf16 hi, lo; split2(v, hi, lo);
            dhi[di] = hi; dlo[di] = lo;
        }
    }
}

// ---------- small kernels ----------
template<int HALF>
__global__ __launch_bounds__(192)
void gather_split(const int* __restrict__ x, const float* __restrict__ emb, bf16* xhi, bf16* xlo)
{
    int row = blockIdx.x, tok = x[row];
    const float* s = emb + (long)tok * U_DIM;
    for (int i = threadIdx.x; i < U_DIM; i += 192) {
        if (HALF) {
            __half hi, lo; split2h(s[i], hi, lo);
            ((__half*)xhi)[(long)row * U_DIM + i] = hi;
            ((__half*)xlo)[(long)row * U_DIM + i] = lo;
        } else {
            bf16 hi, lo; split2(s[i], hi, lo);
            xhi[(long)row * U_DIM + i] = hi; xlo[(long)row * U_DIM + i] = lo;
        }
    }
}
// HALF: fp16 split out; ADD: h := h + add before rms
template<int HALF, int ADD>
__global__ __launch_bounds__(256)
void rms_split(const float* __restrict__ h, const float* __restrict__ add,
               bf16* nhi, bf16* nlo)
{
    __shared__ float row[768];
    long r = blockIdx.x;
    const float* hr = h + r * U_DIM;
    float s = 0.f;
    for (int u = threadIdx.x; u < U_DIM; u += 256) {
        float t = hr[u];
        if (ADD) t += add[r * U_DIM + u];
        row[u] = t;
        s = fmaf(t, t, s);
    }
    s = warpSum(s);
    __shared__ float red[8]; __shared__ float rsh;
    int wid = threadIdx.x >> 5, lane = threadIdx.x & 31;
    if (lane == 0) red[wid] = s;
    __syncthreads();
    if (threadIdx.x == 0) {
        float tot = 0.f;
        #pragma unroll
        for (int i = 0; i < 8; i++) tot += red[i];
        rsh = rsqrtf(tot / (float)U_DIM + EPS_F);
    }
    __syncthreads();
    float rr = rsh;
    for (int u = threadIdx.x; u < U_DIM; u += 256) {
        float o = row[u] * rr;
        if (HALF) {
            __half hi, lo; split2h(o, hi, lo);
            ((__half*)nhi)[r * U_DIM + u] = hi;
            ((__half*)nlo)[r * U_DIM + u] = lo;
        } else {
            bf16 hi, lo; split2(o, hi, lo);
            nhi[r * U_DIM + u] = hi; nlo[r * U_DIM + u] = lo;
        }
    }
}
__global__ __launch_bounds__(256)
void zerok(float* p, int n)
{
    int i = blockIdx.x * 256 + threadIdx.x;
    if (i < n) p[i] = 0.f;
}
__global__ __launch_bounds__(256)
void denk(const bf16* __restrict__ qhi, const bf16* __restrict__ qlo,
          const float* __restrict__ ks, float* den)
{
    int gw = (blockIdx.x * 256 + threadIdx.x) >> 5;
    int lane = threadIdx.x & 31;
    if (gw >= BT) return;
    int b = gw >> 10;
    const bf16* ph = qhi + (long)gw * U_DIM;
    const bf16* pl = qlo + (long)gw * U_DIM;
    const float* kb = ks + b * U_DIM;
    float s = 0.f;
    for (int u = lane; u < U_DIM; u += 32)
        s = fmaf(__bfloat162float(ph[u]) + __bfloat162float(pl[u]), kb[u], s);
    s = warpSum(s);
    if (lane == 0) den[gw] = s + EPS_F;
}

// ---------- host ----------
static void tc(int epi, GArgs& a, int M, int N, int Z)
{
    dim3 g(N / 128, M / 128, Z);
    switch (epi) {
    case 1: mma_gemm<1,2><<<g, 256, DSM>>>(a); break;   // h0: fp16 3-pass
    case 2: mma_gemm<2,0><<<g, 256, DSM>>>(a); break;
    case 7: mma_gemm<7,1><<<g, 256, DSM>>>(a); break;   // logits: fp16 2-pass
    case 8: mma_gemm<8,0><<<g, 256, DSM>>>(a); break;
    }
}

extern "C" void kernel_launch(void* const* d_in, const int* in_sizes, int n_in,
                              void* d_out, int out_size)
{
    const int*   x    = (const int*)  d_in[0];
    const float* emb  = (const float*)d_in[1];
    const float* W_in = (const float*)d_in[2];
    const float* Wq   = (const float*)d_in[3];
    const float* bq   = (const float*)d_in[4];
    const float* Wk   = (const float*)d_in[5];
    const float* bk   = (const float*)d_in[6];
    const float* Wv   = (const float*)d_in[7];
    const float* bv   = (const float*)d_in[8];
    const float* gW   = (const float*)d_in[9];
    const float* gb   = (const float*)d_in[10];
    const float* eW   = (const float*)d_in[11];
    const float* eb   = (const float*)d_in[12];
    const float* fW1  = (const float*)d_in[13];
    const float* fb1  = (const float*)d_in[14];
    const float* fW2  = (const float*)d_in[15];
    const float* fb2  = (const float*)d_in[16];
    const float* Wlog = (const float*)d_in[17];
    float* out = (float*)d_out;

    cudaFuncSetAttribute((const void*)mma_gemm<1,2>, cudaFuncAttributeMaxDynamicSharedMemorySize, DSM);
    cudaFuncSetAttribute((const void*)mma_gemm<2,0>, cudaFuncAttributeMaxDynamicSharedMemorySize, DSM);
    cudaFuncSetAttribute((const void*)mma_gemm<7,1>, cudaFuncAttributeMaxDynamicSharedMemorySize, DSM);
    cudaFuncSetAttribute((const void*)mma_gemm<8,0>, cudaFuncAttributeMaxDynamicSharedMemorySize, DSM);

    bf16 *whi, *wlo, *nhi, *nlo, *xhi, *xlo, *qhi, *qlo, *kthi, *ktlo, *vthi, *vtlo;
    bf16 *kvhi, *kvlo, *f1hi, *f1lo, *amhi, *amlo;
    float *h, *h0, *hA, *hM, *n, *mo, *ksum, *den, *gate;
    cudaGetSymbolAddress((void**)&whi, g_whi);  cudaGetSymbolAddress((void**)&wlo, g_wlo);
    cudaGetSymbolAddress((void**)&h, g_h);      cudaGetSymbolAddress((void**)&h0, g_h0);
    cudaGetSymbolAddress((void**)&hA, g_hA);    cudaGetSymbolAddress((void**)&hM, g_hM);
    cudaGetSymbolAddress((void**)&n, g_n);      cudaGetSymbolAddress((void**)&mo, g_mo);
    cudaGetSymbolAddress((void**)&ksum, g_ksum);
    cudaGetSymbolAddress((void**)&den, g_den);  cudaGetSymbolAddress((void**)&gate, g_gate);
    cudaGetSymbolAddress((void**)&nhi, g_nhi);  cudaGetSymbolAddress((void**)&nlo, g_nlo);
    cudaGetSymbolAddress((void**)&xhi, g_xhi);  cudaGetSymbolAddress((void**)&xlo, g_xlo);
    cudaGetSymbolAddress((void**)&qhi, g_qhi);  cudaGetSymbolAddress((void**)&qlo, g_qlo);
    cudaGetSymbolAddress((void**)&kthi, g_kthi); cudaGetSymbolAddress((void**)&ktlo, g_ktlo);
    cudaGetSymbolAddress((void**)&vthi, g_vthi); cudaGetSymbolAddress((void**)&vtlo, g_vtlo);
    cudaGetSymbolAddress((void**)&kvhi, g_kvhi); cudaGetSymbolAddress((void**)&kvlo, g_kvlo);
    cudaGetSymbolAddress((void**)&f1hi, g_f1hi); cudaGetSymbolAddress((void**)&f1lo, g_f1lo);
    cudaGetSymbolAddress((void**)&amhi, g_amhi); cudaGetSymbolAddress((void**)&amlo, g_amlo);

    GArgs a;
    tsplit<<<dim3(24, 24, 1),   256>>>(W_in, whi + OFF_WIN, wlo + OFF_WIN, 768, 768, 2, UU, 0);
    gather_split<1><<<BT, 192>>>(x, emb, xhi, xlo);
    tsplit<<<dim3(24, 24, 16),  256>>>(Wq, whi + OFF_QKV, wlo + OFF_QKV, 768, 768, 0, 3*UU, 0);
    a = {}; a.Ahi = xhi; a.Alo = xlo; a.Bhi = whi + OFF_WIN; a.Blo = wlo + OFF_WIN;
    a.N = 768; a.K = 768; a.SK = 1; a.outF = h0; a.outF2 = h;
    tc(1, a, BT, 768, 1);                     // launch #3 <- ncu
    tsplit<<<dim3(24, 24, 16),  256>>>(Wk, whi + OFF_QKV, wlo + OFF_QKV, 768, 768, 0, 3*UU, UU);
    tsplit<<<dim3(24, 24, 16),  256>>>(Wv, whi + OFF_QKV, wlo + OFF_QKV, 768, 768, 0, 3*UU, 2*UU);
    tsplit<<<dim3(24, 24, 16),  256>>>(fW1, whi + OFF_F1, wlo + OFF_F1, 768, 768, 0, UU, 0);
    tsplit<<<dim3(24, 24, 16),  256>>>(fW2, whi + OFF_F2, wlo + OFF_F2, 768, 768, 0, UU, 0);
    tsplit<<<dim3(24, 24, 128), 256>>>(eW, whi + OFF_EW, wlo + OFF_EW, 768, 768, 1, 0, 0);
    tsplit<<<dim3(1000, 24, 1), 256>>>(Wlog, whi + OFF_WLOG, wlo + OFF_WLOG, 768, 32000, 2, 0, 0);
    rms_split<0,0><<<BT, 256>>>(h, nullptr, nhi, nlo);

    for (int l = 0; l < L_DIM; l++) {
        zerok<<<6, 256>>>(ksum, 1536);
        a = {}; a.Ahi = nhi; a.Alo = nlo;
        a.Bhi = whi + OFF_QKV + (long)l * 3 * UU; a.Blo = wlo + OFF_QKV + (long)l * 3 * UU;
        a.N = 2304; a.K = 768; a.SK = 1;
        a.bias = bq + l * U_DIM; a.bias2 = bk + l * U_DIM; a.bias3 = bv + l * U_DIM;
        a.oHi = qhi; a.oLo = qlo; a.oHi2 = kthi; a.oLo2 = ktlo; a.oHi3 = vthi; a.oLo3 = vtlo;
        a.ksum = ksum;
        tc(8, a, BT, 2304, 1);
        denk<<<256, 256>>>(qhi, qlo, ksum, den);
        a = {}; a.Ahi = vthi; a.Alo = vtlo; a.Bhi = kthi; a.Blo = ktlo;
        a.N = 768; a.K = 1024; a.kSplit = 512; a.SK = 2; a.aZ = TU; a.bZ = TU; a.cZ = UU;
        a.outF = mo;
        tc(2, a, 768, 768, 4);
        comb<4><<<(int)(2*UU/1024), 256>>>(mo, UU, 2, 2*UU, nullptr, kvhi, kvlo);
        a = {}; a.Ahi = qhi; a.Alo = qlo; a.Bhi = kvhi; a.Blo = kvlo;
        a.N = 768; a.K = 768; a.kSplit = 256; a.SK = 3; a.aZ = TU; a.bZ = UU; a.cZ = TU;
        a.outF = mo;
        tc(2, a, T_DIM, 768, 6);
        combA<0><<<BT, 256>>>(mo, den, h, nullptr, nullptr, nullptr,
                              gW + (long)l * U_DIM * E_DIM, gb + l * E_DIM, nullptr,
                              nullptr, nullptr, nullptr, gate, nullptr, nullptr, amhi, amlo);
        a = {}; a.Ahi = amhi; a.Alo = amlo;
        a.Bhi = whi + OFF_EW + (long)l * 8 * UU; a.Blo = wlo + OFF_EW + (long)l * 8 * UU;
        a.N = 768; a.K = 6144; a.kSplit = 2048; a.SK = 3; a.cZ = HN; a.outF = mo;
        tc(2, a, BT, 768, 3);
        combA<1><<<BT, 256>>>(mo, nullptr, nullptr, nullptr, nullptr,
                              eb + (long)l * E_DIM * U_DIM, nullptr, nullptr, gate,
                              hM, nullptr, nullptr, nullptr, nhi, nlo, nullptr, nullptr);
        a = {}; a.Ahi = nhi; a.Alo = nlo;
        a.Bhi = whi + OFF_F1 + (long)l * UU; a.Blo = wlo + OFF_F1 + (long)l * UU;
        a.N = 768; a.K = 768; a.kSplit = 256; a.SK = 3; a.cZ = HN; a.outF = mo;
        tc(2, a, BT, 768, 3);
        comb<1><<<(int)(HN/1024), 256>>>(mo, HN, 3, HN, fb1 + l * U_DIM, f1hi, f1lo);
        a = {}; a.Ahi = f1hi; a.Alo = f1lo;
        a.Bhi = whi + OFF_F2 + (long)l * UU; a.Blo = wlo + OFF_F2 + (long)l * UU;
        a.N = 768; a.K = 768; a.kSplit = 256; a.SK = 3; a.cZ = HN; a.outF = mo;
        tc(2, a, BT, 768, 3);
        combA<2><<<BT, 256>>>(mo, nullptr, h, hM, fb2 + l * U_DIM, nullptr,
                              nullptr, nullptr, nullptr,
                              nullptr, h, n, nullptr, nhi, nlo, nullptr, nullptr);
    }

    // final: n = rms(h) (from combA<2>); rms(n + h0) -> fp16 split; logits
    rms_split<1,1><<<BT, 256>>>(n, h0, nhi, nlo);
    a = {}; a.Ahi = nhi; a.Alo = nlo; a.Bhi = whi + OFF_WLOG; a.Blo = wlo + OFF_WLOG;
    a.N = 32000; a.K = 768; a.SK = 1; a.outF = out;
    tc(7, a, BT, 32000, 1);
}

// round 15
// speedup vs baseline: 2.5034x; 1.0561x over previous
#include <cuda_runtime.h>
#include <cuda_bf16.h>
#include <cuda_fp16.h>
#include <cstdint>

#define U_DIM 768
#define T_DIM 1024
#define B_DIM 2
#define BT    2048
#define E_DIM 8
#define L_DIM 16
#define V_DIM 32000
#define EPS_F 1e-6f
#define UU    589824L
#define TU    786432L
#define HN    1572864L

#define OFF_WIN  0L
#define OFF_QKV  (UU)
#define OFF_F1   (OFF_QKV + 48L*UU)
#define OFF_F2   (OFF_F1 + 16L*UU)
#define OFF_EW   (OFF_F2 + 16L*UU)
#define OFF_WLOG (OFF_EW + 128L*UU)
#define W_TOTAL  (OFF_WLOG + 32000L*768L)

typedef __nv_bfloat16 bf16;

__device__ bf16 g_whi[W_TOTAL];
__device__ bf16 g_wlo[W_TOTAL];
__device__ float g_h[HN], g_h0[HN], g_hA[HN], g_hM[HN], g_n[HN];
__device__ float g_mo[3*HN];
__device__ float g_ksum[B_DIM*U_DIM], g_den[BT], g_gate[BT*E_DIM];
__device__ bf16 g_nhi[HN],  g_nlo[HN];
__device__ bf16 g_xhi[HN],  g_xlo[HN];
__device__ bf16 g_qhi[HN],  g_qlo[HN];
__device__ bf16 g_kthi[HN], g_ktlo[HN];
__device__ bf16 g_vthi[HN], g_vtlo[HN];
__device__ bf16 g_kvhi[B_DIM*UU], g_kvlo[B_DIM*UU];
__device__ bf16 g_f1hi[HN], g_f1lo[HN];
__device__ bf16 g_amhi[BT*6144L], g_amlo[BT*6144L];

__device__ __forceinline__ uint32_t smem_u32(const void* p) {
    uint32_t a;
    asm("{ .reg .u64 t; cvta.to.shared.u64 t, %1; cvt.u32.u64 %0, t; }" : "=r"(a) : "l"(p));
    return a;
}
__device__ __forceinline__ void split2(float x, bf16& hi, bf16& lo) {
    hi = __float2bfloat16(x);
    lo = __float2bfloat16(x - __bfloat162float(hi));
}
__device__ __forceinline__ void split2h(float x, __half& hi, __half& lo) {
    hi = __float2half(x);
    lo = __float2half(x - __half2float(hi));
}
__device__ __forceinline__ float warpSum(float v) {
    #pragma unroll
    for (int o = 16; o > 0; o >>= 1) v += __shfl_xor_sync(0xffffffffu, v, o);
    return v;
}

struct GArgs {
    const bf16 *Ahi, *Alo, *Bhi, *Blo;
    int N, K, kSplit, SK;
    long aZ, bZ, cZ;
    const float *bias, *bias2, *bias3;
    float *outF, *outF2;
    bf16 *oHi, *oLo, *oHi2, *oLo2, *oHi3, *oLo3;
    float *ksum;
};

#define ROWS 72
#define TB   (128 * ROWS * 2)
#define DSM  (12 * TB)         // 3 stages x 4 tiles = 221184

#define MMA_BF(dv, afv, bfv) \
    asm volatile("mma.sync.aligned.m16n8k16.row.col.f32.bf16.bf16.f32 " \
        "{%0,%1,%2,%3}, {%4,%5,%6,%7}, {%8,%9}, {%0,%1,%2,%3};" \
        : "+f"((dv)[0]), "+f"((dv)[1]), "+f"((dv)[2]), "+f"((dv)[3]) \
        : "r"((afv)[0]), "r"((afv)[1]), "r"((afv)[2]), "r"((afv)[3]), \
          "r"((bfv)[0]), "r"((bfv)[1]))
#define MMA_F16(dv, afv, bfv) \
    asm volatile("mma.sync.aligned.m16n8k16.row.col.f32.f16.f16.f32 " \
        "{%0,%1,%2,%3}, {%4,%5,%6,%7}, {%8,%9}, {%0,%1,%2,%3};" \
        : "+f"((dv)[0]), "+f"((dv)[1]), "+f"((dv)[2]), "+f"((dv)[3]) \
        : "r"((afv)[0]), "r"((afv)[1]), "r"((afv)[2]), "r"((afv)[3]), \
          "r"((bfv)[0]), "r"((bfv)[1]))

// EPI: 1 out(+copy), 2 partial, 7 logits x2, 8 qkv
// PM: 0 = bf16 3-pass, 1 = fp16 2-pass, 2 = fp16 3-pass
template<int EPI, int PM>
__global__ __launch_bounds__(256)
void mma_gemm(GArgs g)
{
    extern __shared__ char smem[];
    uint32_t sb = smem_u32(smem);
    const int tid = threadIdx.x, wid = tid >> 5, lane = tid & 31;
    const int wm = wid >> 2, wn = wid & 3;
    const int z = blockIdx.z;
    const int zB = g.SK > 1 ? z / g.SK : z;
    const int zS = g.SK > 1 ? z % g.SK : 0;
    const int row0 = blockIdx.y * 128, col0 = blockIdx.x * 128;
    const int Nn = g.N, K = g.K;

    const bf16* Ahi = g.Ahi + (long)zB * g.aZ;
    const bf16* Alo = g.Alo + (long)zB * g.aZ;
    const bf16* Bhi = g.Bhi + (long)zB * g.bZ;
    const bf16* Blo = g.Blo + (long)zB * g.bZ;
    const int kbase = g.kSplit ? zS * g.kSplit : 0;
    const int CH = (g.kSplit ? g.kSplit : K) >> 6;

    float d[4][4][4];
    #pragma unroll
    for (int a = 0; a < 4; a++)
        #pragma unroll
        for (int b = 0; b < 4; b++)
            #pragma unroll
            for (int c = 0; c < 4; c++) d[a][b][c] = 0.f;

    auto issue = [&](int c, int s) {
        int k0 = kbase + (c << 6);
        const bf16* srcs[4] = {
            Ahi + (long)row0 * K + k0, Alo + (long)row0 * K + k0,
            Bhi + (long)col0 * K + k0, Blo + (long)col0 * K + k0 };
        #pragma unroll
        for (int t = 0; t < 4; t++) {
            if (PM == 1 && t == 1) continue;
            uint32_t dst = sb + (uint32_t)(s * 4 + t) * TB;
            #pragma unroll
            for (int i = 0; i < 4; i++) {
                int idx = tid + (i << 8);
                int r = idx >> 3, cc = idx & 7;
                uint32_t doff = (uint32_t)(r * ROWS + cc * 8) * 2;
                const void* sp = srcs[t] + (long)r * K + cc * 8;
                asm volatile("cp.async.cg.shared.global [%0], [%1], 16;"
                             :: "r"(dst + doff), "l"(sp));
            }
        }
        asm volatile("cp.async.commit_group;");
    };

    issue(0, 0);
    if (CH > 1) issue(1, 1);
    for (int c = 0; c < CH; c++) {
        int s = c % 3;
        if (c + 2 < CH) { issue(c + 2, (c + 2) % 3); asm volatile("cp.async.wait_group 2;"); }
        else if (c + 1 < CH) { asm volatile("cp.async.wait_group 1;"); }
        else { asm volatile("cp.async.wait_group 0;"); }
        __syncthreads();
        uint32_t bAH = sb + (uint32_t)(s * 4 + 0) * TB;
        uint32_t bAL = sb + (uint32_t)(s * 4 + 1) * TB;
        uint32_t bBH = sb + (uint32_t)(s * 4 + 2) * TB;
        uint32_t bBL = sb + (uint32_t)(s * 4 + 3) * TB;
        #pragma unroll
        for (int ks = 0; ks < 4; ks++) {
            int k16 = ks * 16;
            int aoff = (wm * 64 + (lane & 15)) * ROWS + k16 + ((lane >> 4) << 3);
            int boff = (wn * 32 + (lane & 7)) * ROWS + k16 + (((lane >> 3) & 1) << 3);
            uint32_t af[4][4], af2[4][4], bf_[4][2];
            #pragma unroll
            for (int mt = 0; mt < 4; mt++) {
                uint32_t ad = bAH + (uint32_t)(aoff + mt * 16 * ROWS) * 2;
                asm volatile("ldmatrix.sync.aligned.m8n8.x4.shared.b16 {%0,%1,%2,%3}, [%4];"
                    : "=r"(af[mt][0]), "=r"(af[mt][1]), "=r"(af[mt][2]), "=r"(af[mt][3]) : "r"(ad));
            }
            #pragma unroll
            for (int nt = 0; nt < 4; nt++) {
                uint32_t bd = bBH + (uint32_t)(boff + nt * 8 * ROWS) * 2;
                asm volatile("ldmatrix.sync.aligned.m8n8.x2.shared.b16 {%0,%1}, [%2];"
                    : "=r"(bf_[nt][0]), "=r"(bf_[nt][1]) : "r"(bd));
            }
            #pragma unroll
            for (int mt = 0; mt < 4; mt++)
                #pragma unroll
                for (int nt = 0; nt < 4; nt++) {
                    if (PM) { MMA_F16(d[mt][nt], af[mt], bf_[nt]); }
                    else    { MMA_BF (d[mt][nt], af[mt], bf_[nt]); }
                }
            if (PM != 1) {
                #pragma unroll
                for (int mt = 0; mt < 4; mt++) {
                    uint32_t ad = bAL + (uint32_t)(aoff + mt * 16 * ROWS) * 2;
                    asm volatile("ldmatrix.sync.aligned.m8n8.x4.shared.b16 {%0,%1,%2,%3}, [%4];"
                        : "=r"(af2[mt][0]), "=r"(af2[mt][1]), "=r"(af2[mt][2]), "=r"(af2[mt][3]) : "r"(ad));
                }
                #pragma unroll
                for (int mt = 0; mt < 4; mt++)
                    #pragma unroll
                    for (int nt = 0; nt < 4; nt++) {
                        if (PM) { MMA_F16(d[mt][nt], af2[mt], bf_[nt]); }
                        else    { MMA_BF (d[mt][nt], af2[mt], bf_[nt]); }
                    }
            }
            #pragma unroll
            for (int nt = 0; nt < 4; nt++) {
                uint32_t bd = bBL + (uint32_t)(boff + nt * 8 * ROWS) * 2;
                asm volatile("ldmatrix.sync.aligned.m8n8.x2.shared.b16 {%0,%1}, [%2];"
                    : "=r"(bf_[nt][0]), "=r"(bf_[nt][1]) : "r"(bd));
            }
            #pragma unroll
            for (int mt = 0; mt < 4; mt++)
                #pragma unroll
                for (int nt = 0; nt < 4; nt++) {
                    if (PM) { MMA_F16(d[mt][nt], af[mt], bf_[nt]); }
                    else    { MMA_BF (d[mt][nt], af[mt], bf_[nt]); }
                }
        }
        __syncthreads();
    }

    // ---------------- epilogues ----------------
    if (EPI == 8) {
        const int blkN = col0 / 768;
        const int cc0  = col0 - blkN * 768;
        if (blkN == 0) {
            #pragma unroll
            for (int mt = 0; mt < 4; mt++)
                #pragma unroll
                for (int half = 0; half < 2; half++) {
                    int rg = row0 + wm * 64 + mt * 16 + (lane >> 2) + half * 8;
                    #pragma unroll
                    for (int nt = 0; nt < 4; nt++) {
                        int col = cc0 + wn * 32 + nt * 8 + 2 * (lane & 3);
                        float t0 = d[mt][nt][half*2+0] + __ldg(&g.bias[col]);
                        float t1 = d[mt][nt][half*2+1] + __ldg(&g.bias[col+1]);
                        float o0 = (t0 > 0.f) ? (t0 + 1.f) : __expf(t0);
                        float o1 = (t1 > 0.f) ? (t1 + 1.f) : __expf(t1);
                        bf16 h0b,l0b,h1b,l1b; split2(o0,h0b,l0b); split2(o1,h1b,l1b);
                        __nv_bfloat162 ph; ph.x=h0b; ph.y=h1b;
                        __nv_bfloat162 pl; pl.x=l0b; pl.y=l1b;
                        long idx = (long)rg * 768 + col;
                        *(__nv_bfloat162*)(g.oHi + idx) = ph;
                        *(__nv_bfloat162*)(g.oLo + idx) = pl;
                    }
                }
        } else {
            const float* bp = (blkN == 1) ? g.bias2 : g.bias3;
            float* tile = (float*)smem;
            #pragma unroll
            for (int mt = 0; mt < 4; mt++)
                #pragma unroll
                for (int nt = 0; nt < 4; nt++)
                    #pragma unroll
                    for (int half = 0; half < 2; half++)
                        #pragma unroll
                        for (int jj = 0; jj < 2; jj++) {
                            int r = wm*64 + mt*16 + (lane>>2) + half*8;
                            int cl = wn*32 + nt*8 + 2*(lane&3) + jj;
                            float t = d[mt][nt][half*2+jj] + __ldg(&bp[cc0 + cl]);
                            if (blkN == 1) t = (t > 0.f) ? (t + 1.f) : __expf(t);
                            tile[r * 130 + cl] = t;
                        }
            __syncthreads();
            bf16* dh = (blkN == 1) ? g.oHi2 : g.oHi3;
            bf16* dl = (blkN == 1) ? g.oLo2 : g.oLo3;
            int u_l = tid & 127, th = tid >> 7;
            int bb = row0 >> 10, t0 = row0 & 1023;
            long rowbase = ((long)(bb * 768 + cc0 + u_l)) * 1024 + t0 + th * 64;
            uint32_t hb[32], lb[32];
            float csum = 0.f;
            #pragma unroll
            for (int j = 0; j < 64; j += 2) {
                float v0 = tile[(th*64 + j) * 130 + u_l];
                float v1 = tile[(th*64 + j + 1) * 130 + u_l];
                if (blkN == 1) csum += v0 + v1;
                bf16 h0b,l0b,h1b,l1b; split2(v0,h0b,l0b); split2(v1,h1b,l1b);
                __nv_bfloat162 ph; ph.x=h0b; ph.y=h1b;
                __nv_bfloat162 pl; pl.x=l0b; pl.y=l1b;
                hb[j>>1] = *(uint32_t*)&ph; lb[j>>1] = *(uint32_t*)&pl;
            }
            uint4* dh4 = (uint4*)(dh + rowbase);
            uint4* dl4 = (uint4*)(dl + rowbase);
            #pragma unroll
            for (int i = 0; i < 8; i++) { dh4[i] = ((uint4*)hb)[i]; dl4[i] = ((uint4*)lb)[i]; }
            if (blkN == 1) atomicAdd(&g.ksum[bb * 768 + cc0 + u_l], csum);
        }
        return;
    }

    float* outF = g.outF + (long)z * g.cZ;
    #pragma unroll
    for (int mt = 0; mt < 4; mt++)
        #pragma unroll
        for (int half = 0; half < 2; half++) {
            int rg = row0 + wm * 64 + mt * 16 + (lane >> 2) + half * 8;
            #pragma unroll
            for (int nt = 0; nt < 4; nt++) {
                int col = col0 + wn * 32 + nt * 8 + 2 * (lane & 3);
                long idx = (long)rg * Nn + col;
                float2 v2;
                v2.x = d[mt][nt][half*2+0];
                v2.y = d[mt][nt][half*2+1];
                if (EPI == 7) { v2.x *= 2.0f; v2.y *= 2.0f; }
                *(float2*)(outF + idx) = v2;
                if (EPI == 1 && g.outF2) *(float2*)(g.outF2 + idx) = v2;
            }
        }
}

// ---------- row-fused combines ----------
template<int MODE>
__global__ __launch_bounds__(256)
void combA(const float* __restrict__ mo, const float* __restrict__ den,
           const float* __restrict__ hOld, const float* __restrict__ hMin,
           const float* __restrict__ bias, const float* __restrict__ eb,
           const float* __restrict__ gWl, const float* __restrict__ gbl,
           const float* __restrict__ gateIn,
           float* hMout, float* hOut, float* nOut, float* gateOut,
           bf16* nhi, bf16* nlo, bf16* amhi, bf16* amlo)
{
    __shared__ float row[768];
    __shared__ float red[8]; __shared__ float rsh; __shared__ float gsl[8][8];
    __shared__ float gfin[8];
    int r = blockIdx.x, tid = threadIdx.x;
    int wid = tid >> 5, lane = tid & 31;
    int b = r >> 10, t = r & 1023;
    // vectorized combine: 192 threads x float4 cover 768
    if (tid < 192) {
        int u = tid * 4;
        float4 v;
        if (MODE == 0) {
            long base = (long)(b * 3) * TU + (long)t * 768 + u;
            float4 p0 = *(const float4*)(mo + base);
            float4 p1 = *(const float4*)(mo + base + TU);
            float4 p2 = *(const float4*)(mo + base + 2 * TU);
            float dn = den[r];
            float4 hv = *(const float4*)(hOld + (long)r * 768 + u);
            v.x = (p0.x + p1.x + p2.x) / dn + hv.x;
            v.y = (p0.y + p1.y + p2.y) / dn + hv.y;
            v.z = (p0.z + p1.z + p2.z) / dn + hv.z;
            v.w = (p0.w + p1.w + p2.w) / dn + hv.w;
        } else {
            long base = (long)r * 768 + u;
            float4 p0 = *(const float4*)(mo + base);
            float4 p1 = *(const float4*)(mo + base + HN);
            float4 p2 = *(const float4*)(mo + base + 2 * HN);
            v.x = p0.x + p1.x + p2.x;
            v.y = p0.y + p1.y + p2.y;
            v.z = p0.z + p1.z + p2.z;
            v.w = p0.w + p1.w + p2.w;
            if (MODE == 1) {
                float gv[8];
                #pragma unroll
                for (int e = 0; e < 8; e++) gv[e] = gateIn[(long)r * 8 + e];
                float bm[4] = {0.f, 0.f, 0.f, 0.f};
                #pragma unroll
                for (int e = 0; e < 8; e++) {
                    float4 ebv = *(const float4*)(eb + e * 768 + u);
                    bm[0] = fmaf(gv[e], ebv.x, bm[0]);
                    bm[1] = fmaf(gv[e], ebv.y, bm[1]);
                    bm[2] = fmaf(gv[e], ebv.z, bm[2]);
                    bm[3] = fmaf(gv[e], ebv.w, bm[3]);
                }
                v.x += bm[0]; v.y += bm[1]; v.z += bm[2]; v.w += bm[3];
                *(float4*)(hMout + base) = v;
            } else {
                float4 bv = *(const float4*)(bias + u);
                float4 hm = *(const float4*)(hMin + base);
                float4 hv = *(const float4*)(hOld + base);
                v.x = 1.f / (1.f + __expf(-(v.x + bv.x))) + hm.x + hv.x;
                v.y = 1.f / (1.f + __expf(-(v.y + bv.y))) + hm.y + hv.y;
                v.z = 1.f / (1.f + __expf(-(v.z + bv.z))) + hm.z + hv.z;
                v.w = 1.f / (1.f + __expf(-(v.w + bv.w))) + hm.w + hv.w;
                *(float4*)(hOut + base) = v;
            }
        }
        *(float4*)(row + u) = v;
    }
    __syncthreads();
    float s = 0.f;
    for (int u = tid; u < 768; u += 256) { float x = row[u]; s = fmaf(x, x, s); }
    s = warpSum(s);
    if (lane == 0) red[wid] = s;
    __syncthreads();
    if (tid == 0) {
        float tot = 0.f;
        #pragma unroll
        for (int i = 0; i < 8; i++) tot += red[i];
        rsh = rsqrtf(tot / 768.f + EPS_F);
    }
    __syncthreads();
    float rr = rsh;
    if (MODE != 0) {
        for (int u = tid; u < 768; u += 256) {
            float o = row[u] * rr;
            if (MODE == 2) nOut[(long)r * 768 + u] = o;
            bf16 hi, lo; split2(o, hi, lo);
            nhi[(long)r * 768 + u] = hi; nlo[(long)r * 768 + u] = lo;
        }
        return;
    }
    float ge[8];
    #pragma unroll
    for (int e = 0; e < 8; e++) ge[e] = 0.f;
    for (int u = tid; u < 768; u += 256) {
        float o = row[u] * rr;
        #pragma unroll
        for (int e = 0; e < 8; e++) ge[e] = fmaf(o, __ldg(&gWl[u * 8 + e]), ge[e]);
    }
    #pragma unroll
    for (int e = 0; e < 8; e++) ge[e] = warpSum(ge[e]);
    if (lane < 8) gsl[wid][lane] = ge[lane];
    __syncthreads();
    if (tid == 0) {
        float sl[8];
        #pragma unroll
        for (int e = 0; e < 8; e++) {
            float tt = gbl[e];
            #pragma unroll
            for (int w = 0; w < 8; w++) tt += gsl[w][e];
            sl[e] = tt;
        }
        float mx = sl[0];
        #pragma unroll
        for (int e = 1; e < 8; e++) mx = fmaxf(mx, sl[e]);
        float ex[8], sum = 0.f;
        #pragma unroll
        for (int e = 0; e < 8; e++) { ex[e] = __expf(sl[e] - mx); sum += ex[e]; }
        float inv = 1.f / sum;
        #pragma unroll
        for (int e = 0; e < 8; e++) { float gv = ex[e] * inv; gfin[e] = gv; gateOut[(long)r * 8 + e] = gv; }
    }
    __syncthreads();
    long abase = (long)r * 6144;
    for (int i = tid; i < 3072; i += 256) {
        int e = i / 384, u2 = (i % 384) * 2;
        float gv = gfin[e];
        float o0 = row[u2] * rr * gv, o1 = row[u2 + 1] * rr * gv;
        bf16 h0b,l0b,h1b,l1b; split2(o0,h0b,l0b); split2(o1,h1b,l1b);
        __nv_bfloat162 ph; ph.x=h0b; ph.y=h1b;
        __nv_bfloat162 pl; pl.x=l0b; pl.y=l1b;
        *(__nv_bfloat162*)(amhi + abase + e * 768 + u2) = ph;
        *(__nv_bfloat162*)(amlo + abase + e * 768 + u2) = pl;
    }
}

template<int MODE>
__global__ __launch_bounds__(256)
void comb(const float* __restrict__ p, long segZ, int ns, long total,
          const float* __restrict__ bias, bf16* oHi, bf16* oLo)
{
    long i4 = ((long)blockIdx.x * 256 + threadIdx.x) * 4;
    if (i4 >= total) return;
    long base = (i4 / segZ) * (long)ns * segZ + (i4 % segZ);
    float4 s = *(const float4*)(p + base);
    float4 s1 = *(const float4*)(p + base + segZ);
    s.x += s1.x; s.y += s1.y; s.z += s1.z; s.w += s1.w;
    if (ns == 3) {
        float4 s2 = *(const float4*)(p + base + 2 * segZ);
        s.x += s2.x; s.y += s2.y; s.z += s2.z; s.w += s2.w;
    }
    float v[4] = {s.x, s.y, s.z, s.w};
    int col = (int)(i4 % 768);
    bf16 hh[4], ll[4];
    #pragma unroll
    for (int j = 0; j < 4; j++) {
        float o = v[j];
        if (MODE == 1) { float t = o + __ldg(&bias[col + j]); o = 1.f / (1.f + __expf(-t)); }
        split2(o, hh[j], ll[j]);
    }
    *(uint2*)(oHi + i4) = *(uint2*)hh;
    *(uint2*)(oLo + i4) = *(uint2*)ll;
}

// ---------- prepack ----------
__global__ __launch_bounds__(256)
void tsplit(const float* __restrict__ src, bf16* dhi, bf16* dlo, int K, int N,
            int mode, long outZ, long rowOff)
{
    __shared__ float t[32][33];
    int z = blockIdx.z;
    const float* s = src + (long)z * K * N;
    long dbase; int dld;
    if (mode == 1) { int l = z >> 3, e = z & 7; dbase = (long)l * 8 * UU + (long)e * U_DIM; dld = 6144; }
    else { dbase = (long)z * outZ + rowOff; dld = K; }
    int n0 = blockIdx.x * 32, k0 = blockIdx.y * 32;
    int tx = threadIdx.x & 31, ty = threadIdx.x >> 5;
    #pragma unroll
    for (int i = 0; i < 32; i += 8) t[ty + i][tx] = s[(long)(k0 + ty + i) * N + n0 + tx];
    __syncthreads();
    #pragma unroll
    for (int i = 0; i < 32; i += 8) {
        float v = t[tx][ty + i];
        long di = dbase + (long)(n0 + ty + i) * dld + k0 + tx;
        if (mode == 2) {
            __half hi, lo; split2h(v, hi, lo);
            ((__half*)dhi)[di] = hi; ((__half*)dlo)[di] = lo;
        } else {
            bf16 hi, lo; split2(v, hi, lo);
            dhi[di] = hi; dlo[di] = lo;
        }
    }
}

// ---------- small kernels ----------
template<int HALF>
__global__ __launch_bounds__(192)
void gather_split(const int* __restrict__ x, const float* __restrict__ emb, bf16* xhi, bf16* xlo)
{
    int row = blockIdx.x, tok = x[row];
    const float* s = emb + (long)tok * U_DIM;
    for (int i = threadIdx.x; i < U_DIM; i += 192) {
        if (HALF) {
            __half hi, lo; split2h(s[i], hi, lo);
            ((__half*)xhi)[(long)row * U_DIM + i] = hi;
            ((__half*)xlo)[(long)row * U_DIM + i] = lo;
        } else {
            bf16 hi, lo; split2(s[i], hi, lo);
            xhi[(long)row * U_DIM + i] = hi; xlo[(long)row * U_DIM + i] = lo;
        }
    }
}
// HALF: fp16 split out; ADD: h := h + add before rms
template<int HALF, int ADD>
__global__ __launch_bounds__(256)
void rms_split(const float* __restrict__ h, const float* __restrict__ add,
               bf16* nhi, bf16* nlo)
{
    __shared__ float row[768];
    long r = blockIdx.x;
    const float* hr = h + r * U_DIM;
    float s = 0.f;
    if (threadIdx.x < 192) {
        int u = threadIdx.x * 4;
        float4 v = *(const float4*)(hr + u);
        if (ADD) {
            float4 a2 = *(const float4*)(add + r * U_DIM + u);
            v.x += a2.x; v.y += a2.y; v.z += a2.z; v.w += a2.w;
        }
        *(float4*)(row + u) = v;
        s = v.x*v.x + v.y*v.y + v.z*v.z + v.w*v.w;
    }
    s = warpSum(s);
    __shared__ float red[8]; __shared__ float rsh;
    int wid = threadIdx.x >> 5, lane = threadIdx.x & 31;
    if (lane == 0) red[wid] = s;
    __syncthreads();
    if (threadIdx.x == 0) {
        float tot = 0.f;
        #pragma unroll
        for (int i = 0; i < 8; i++) tot += red[i];
        rsh = rsqrtf(tot / (float)U_DIM + EPS_F);
    }
    __syncthreads();
    float rr = rsh;
    for (int u = threadIdx.x; u < U_DIM; u += 256) {
        float o = row[u] * rr;
        if (HALF) {
            __half hi, lo; split2h(o, hi, lo);
            ((__half*)nhi)[r * U_DIM + u] = hi;
            ((__half*)nlo)[r * U_DIM + u] = lo;
        } else {
            bf16 hi, lo; split2(o, hi, lo);
            nhi[r * U_DIM + u] = hi; nlo[r * U_DIM + u] = lo;
        }
    }
}
__global__ __launch_bounds__(256)
void zerok(float* p, int n)
{
    int i = blockIdx.x * 256 + threadIdx.x;
    if (i < n) p[i] = 0.f;
}
__global__ __launch_bounds__(256)
void denk(const bf16* __restrict__ qhi, const bf16* __restrict__ qlo,
          const float* __restrict__ ks, float* den)
{
    int gw = (blockIdx.x * 256 + threadIdx.x) >> 5;
    int lane = threadIdx.x & 31;
    if (gw >= BT) return;
    int b = gw >> 10;
    const bf16* ph = qhi + (long)gw * U_DIM;
    const bf16* pl = qlo + (long)gw * U_DIM;
    const float* kb = ks + b * U_DIM;
    float s = 0.f;
    for (int u = lane; u < U_DIM; u += 32)
        s = fmaf(__bfloat162float(ph[u]) + __bfloat162float(pl[u]), kb[u], s);
    s = warpSum(s);
    if (lane == 0) den[gw] = s + EPS_F;
}

// ---------- host ----------
static void tc(int epi, GArgs& a, int M, int N, int Z)
{
    dim3 g(N / 128, M / 128, Z);
    switch (epi) {
    case 1: mma_gemm<1,2><<<g, 256, DSM>>>(a); break;   // h0: fp16 3-pass
    case 2: mma_gemm<2,0><<<g, 256, DSM>>>(a); break;
    case 7: mma_gemm<7,1><<<g, 256, DSM>>>(a); break;   // logits: fp16 2-pass
    case 8: mma_gemm<8,0><<<g, 256, DSM>>>(a); break;
    }
}

extern "C" void kernel_launch(void* const* d_in, const int* in_sizes, int n_in,
                              void* d_out, int out_size)
{
    const int*   x    = (const int*)  d_in[0];
    const float* emb  = (const float*)d_in[1];
    const float* W_in = (const float*)d_in[2];
    const float* Wq   = (const float*)d_in[3];
    const float* bq   = (const float*)d_in[4];
    const float* Wk   = (const float*)d_in[5];
    const float* bk   = (const float*)d_in[6];
    const float* Wv   = (const float*)d_in[7];
    const float* bv   = (const float*)d_in[8];
    const float* gW   = (const float*)d_in[9];
    const float* gb   = (const float*)d_in[10];
    const float* eW   = (const float*)d_in[11];
    const float* eb   = (const float*)d_in[12];
    const float* fW1  = (const float*)d_in[13];
    const float* fb1  = (const float*)d_in[14];
    const float* fW2  = (const float*)d_in[15];
    const float* fb2  = (const float*)d_in[16];
    const float* Wlog = (const float*)d_in[17];
    float* out = (float*)d_out;

    cudaFuncSetAttribute((const void*)mma_gemm<1,2>, cudaFuncAttributeMaxDynamicSharedMemorySize, DSM);
    cudaFuncSetAttribute((const void*)mma_gemm<2,0>, cudaFuncAttributeMaxDynamicSharedMemorySize, DSM);
    cudaFuncSetAttribute((const void*)mma_gemm<7,1>, cudaFuncAttributeMaxDynamicSharedMemorySize, DSM);
    cudaFuncSetAttribute((const void*)mma_gemm<8,0>, cudaFuncAttributeMaxDynamicSharedMemorySize, DSM);

    bf16 *whi, *wlo, *nhi, *nlo, *xhi, *xlo, *qhi, *qlo, *kthi, *ktlo, *vthi, *vtlo;
    bf16 *kvhi, *kvlo, *f1hi, *f1lo, *amhi, *amlo;
    float *h, *h0, *hA, *hM, *n, *mo, *ksum, *den, *gate;
    cudaGetSymbolAddress((void**)&whi, g_whi);  cudaGetSymbolAddress((void**)&wlo, g_wlo);
    cudaGetSymbolAddress((void**)&h, g_h);      cudaGetSymbolAddress((void**)&h0, g_h0);
    cudaGetSymbolAddress((void**)&hA, g_hA);    cudaGetSymbolAddress((void**)&hM, g_hM);
    cudaGetSymbolAddress((void**)&n, g_n);      cudaGetSymbolAddress((void**)&mo, g_mo);
    cudaGetSymbolAddress((void**)&ksum, g_ksum);
    cudaGetSymbolAddress((void**)&den, g_den);  cudaGetSymbolAddress((void**)&gate, g_gate);
    cudaGetSymbolAddress((void**)&nhi, g_nhi);  cudaGetSymbolAddress((void**)&nlo, g_nlo);
    cudaGetSymbolAddress((void**)&xhi, g_xhi);  cudaGetSymbolAddress((void**)&xlo, g_xlo);
    cudaGetSymbolAddress((void**)&qhi, g_qhi);  cudaGetSymbolAddress((void**)&qlo, g_qlo);
    cudaGetSymbolAddress((void**)&kthi, g_kthi); cudaGetSymbolAddress((void**)&ktlo, g_ktlo);
    cudaGetSymbolAddress((void**)&vthi, g_vthi); cudaGetSymbolAddress((void**)&vtlo, g_vtlo);
    cudaGetSymbolAddress((void**)&kvhi, g_kvhi); cudaGetSymbolAddress((void**)&kvlo, g_kvlo);
    cudaGetSymbolAddress((void**)&f1hi, g_f1hi); cudaGetSymbolAddress((void**)&f1lo, g_f1lo);
    cudaGetSymbolAddress((void**)&amhi, g_amhi); cudaGetSymbolAddress((void**)&amlo, g_amlo);

    GArgs a;
    tsplit<<<dim3(24, 24, 1),   256>>>(W_in, whi + OFF_WIN, wlo + OFF_WIN, 768, 768, 2, UU, 0);
    gather_split<1><<<BT, 192>>>(x, emb, xhi, xlo);
    tsplit<<<dim3(24, 24, 16),  256>>>(Wq, whi + OFF_QKV, wlo + OFF_QKV, 768, 768, 0, 3*UU, 0);
    a = {}; a.Ahi = xhi; a.Alo = xlo; a.Bhi = whi + OFF_WIN; a.Blo = wlo + OFF_WIN;
    a.N = 768; a.K = 768; a.SK = 1; a.outF = h0; a.outF2 = h;
    tc(1, a, BT, 768, 1);                     // launch #3 <- ncu
    tsplit<<<dim3(24, 24, 16),  256>>>(Wk, whi + OFF_QKV, wlo + OFF_QKV, 768, 768, 0, 3*UU, UU);
    tsplit<<<dim3(24, 24, 16),  256>>>(Wv, whi + OFF_QKV, wlo + OFF_QKV, 768, 768, 0, 3*UU, 2*UU);
    tsplit<<<dim3(24, 24, 16),  256>>>(fW1, whi + OFF_F1, wlo + OFF_F1, 768, 768, 0, UU, 0);
    tsplit<<<dim3(24, 24, 16),  256>>>(fW2, whi + OFF_F2, wlo + OFF_F2, 768, 768, 0, UU, 0);
    tsplit<<<dim3(24, 24, 128), 256>>>(eW, whi + OFF_EW, wlo + OFF_EW, 768, 768, 1, 0, 0);
    tsplit<<<dim3(1000, 24, 1), 256>>>(Wlog, whi + OFF_WLOG, wlo + OFF_WLOG, 768, 32000, 2, 0, 0);
    rms_split<0,0><<<BT, 256>>>(h, nullptr, nhi, nlo);

    for (int l = 0; l < L_DIM; l++) {
        zerok<<<6, 256>>>(ksum, 1536);
        a = {}; a.Ahi = nhi; a.Alo = nlo;
        a.Bhi = whi + OFF_QKV + (long)l * 3 * UU; a.Blo = wlo + OFF_QKV + (long)l * 3 * UU;
        a.N = 2304; a.K = 768; a.SK = 1;
        a.bias = bq + l * U_DIM; a.bias2 = bk + l * U_DIM; a.bias3 = bv + l * U_DIM;
        a.oHi = qhi; a.oLo = qlo; a.oHi2 = kthi; a.oLo2 = ktlo; a.oHi3 = vthi; a.oLo3 = vtlo;
        a.ksum = ksum;
        tc(8, a, BT, 2304, 1);
        denk<<<256, 256>>>(qhi, qlo, ksum, den);
        a = {}; a.Ahi = vthi; a.Alo = vtlo; a.Bhi = kthi; a.Blo = ktlo;
        a.N = 768; a.K = 1024; a.kSplit = 512; a.SK = 2; a.aZ = TU; a.bZ = TU; a.cZ = UU;
        a.outF = mo;
        tc(2, a, 768, 768, 4);
        comb<4><<<(int)(2*UU/1024), 256>>>(mo, UU, 2, 2*UU, nullptr, kvhi, kvlo);
        a = {}; a.Ahi = qhi; a.Alo = qlo; a.Bhi = kvhi; a.Blo = kvlo;
        a.N = 768; a.K = 768; a.kSplit = 256; a.SK = 3; a.aZ = TU; a.bZ = UU; a.cZ = TU;
        a.outF = mo;
        tc(2, a, T_DIM, 768, 6);
        combA<0><<<BT, 256>>>(mo, den, h, nullptr, nullptr, nullptr,
                              gW + (long)l * U_DIM * E_DIM, gb + l * E_DIM, nullptr,
                              nullptr, nullptr, nullptr, gate, nullptr, nullptr, amhi, amlo);
        a = {}; a.Ahi = amhi; a.Alo = amlo;
        a.Bhi = whi + OFF_EW + (long)l * 8 * UU; a.Blo = wlo + OFF_EW + (long)l * 8 * UU;
        a.N = 768; a.K = 6144; a.kSplit = 2048; a.SK = 3; a.cZ = HN; a.outF = mo;
        tc(2, a, BT, 768, 3);
        combA<1><<<BT, 256>>>(mo, nullptr, nullptr, nullptr, nullptr,
                              eb + (long)l * E_DIM * U_DIM, nullptr, nullptr, gate,
                              hM, nullptr, nullptr, nullptr, nhi, nlo, nullptr, nullptr);
        a = {}; a.Ahi = nhi; a.Alo = nlo;
        a.Bhi = whi + OFF_F1 + (long)l * UU; a.Blo = wlo + OFF_F1 + (long)l * UU;
        a.N = 768; a.K = 768; a.kSplit = 256; a.SK = 3; a.cZ = HN; a.outF = mo;
        tc(2, a, BT, 768, 3);
        comb<1><<<(int)(HN/1024), 256>>>(mo, HN, 3, HN, fb1 + l * U_DIM, f1hi, f1lo);
        a = {}; a.Ahi = f1hi; a.Alo = f1lo;
        a.Bhi = whi + OFF_F2 + (long)l * UU; a.Blo = wlo + OFF_F2 + (long)l * UU;
        a.N = 768; a.K = 768; a.kSplit = 256; a.SK = 3; a.cZ = HN; a.outF = mo;
        tc(2, a, BT, 768, 3);
        combA<2><<<BT, 256>>>(mo, nullptr, h, hM, fb2 + l * U_DIM, nullptr,
                              nullptr, nullptr, nullptr,
                              nullptr, h, n, nullptr, nhi, nlo, nullptr, nullptr);
    }

    // final: n = rms(h) (from combA<2>); rms(n + h0) -> fp16 split; logits
    rms_split<1,1><<<BT, 256>>>(n, h0, nhi, nlo);
    a = {}; a.Ahi = nhi; a.Alo = nlo; a.Bhi = whi + OFF_WLOG; a.Blo = wlo + OFF_WLOG;
    a.N = 32000; a.K = 768; a.SK = 1; a.outF = out;
    tc(7, a, BT, 32000, 1);
}